// round 7
// baseline (speedup 1.0000x reference)
#include <cuda_runtime.h>
#include <cuda_fp16.h>
#include <math.h>

#define HW   128
#define HW2  (128*128)
#define NB   8
#define NT   16
#define PSTR 408    // smem plane-pair stride (words)
#define RSTR 40     // smem row stride (words)

typedef unsigned int uint;

// fp32 state + per-layer z scratch
__device__ float g_h0[NB*32*HW2];
__device__ float g_h1[NB*32*HW2];
__device__ float g_z0[NB*32*HW2];
__device__ float g_z1[NB*32*HW2];
// packed half2 plane-pair mirrors [b][16][HW2]
__device__ uint g_hp0a[NB*16*HW2];   // h0 mirror, parity 0
__device__ uint g_hp0b[NB*16*HW2];   // h0 mirror, parity 1
__device__ uint g_hp1 [NB*16*HW2];   // h1 mirror
__device__ uint g_rhp0[NB*16*HW2];   // rh scratch layer0
__device__ uint g_rhp1[NB*16*HW2];   // rh scratch layer1

// Pre-swizzled weight fragments (f16x2, m16n8k16 A layout)
__device__ uint4 g_wf_g0[9 * 3 * 2 * 2 * 32];
__device__ uint4 g_wf_c0[9 * 3 * 1 * 2 * 32];
__device__ uint4 g_wf_g1[9 * 4 * 2 * 2 * 32];
__device__ uint4 g_wf_c1[9 * 4 * 1 * 2 * 32];

__global__ void zero_states_kernel() {
    size_t i = (size_t)blockIdx.x * blockDim.x + threadIdx.x;   // 1,048,576 threads
    float4 z4 = make_float4(0.f, 0.f, 0.f, 0.f);
    ((float4*)g_h0)[i] = z4;
    ((float4*)g_h1)[i] = z4;
    if (i < (size_t)NB*16*HW2/4) {
        uint4 u4 = make_uint4(0, 0, 0, 0);
        ((uint4*)g_hp0a)[i] = u4;
        ((uint4*)g_hp0b)[i] = u4;
        ((uint4*)g_hp1 )[i] = u4;
    }
}

__device__ __forceinline__ float sigf(float v) {
    return 1.0f / (1.0f + __expf(-v));
}
__device__ __forceinline__ float tanhfast(float v) {
    return 1.0f - 2.0f / (__expf(2.0f * v) + 1.0f);
}
__device__ __forceinline__ uint h2u(float lo, float hi) {
    __half2 h = __halves2half2(__float2half_rn(lo), __float2half_rn(hi));
    return *(uint*)&h;
}
__device__ __forceinline__ void mma16(float* c, uint a0, uint a1, uint a2, uint a3,
                                      uint b0, uint b1) {
    asm volatile(
        "mma.sync.aligned.m16n8k16.row.col.f32.f16.f16.f32 "
        "{%0,%1,%2,%3},{%4,%5,%6,%7},{%8,%9},{%0,%1,%2,%3};"
        : "+f"(c[0]), "+f"(c[1]), "+f"(c[2]), "+f"(c[3])
        : "r"(a0), "r"(a1), "r"(a2), "r"(a3), "r"(b0), "r"(b1));
}

// Virtual plane k -> weight cin.
// L0: k==0 -> x (cw 0); 2<=k<34 -> h (cw k-1); else zero-pad.
// L1: k -> k.
template<int KTOT, int COUT, int CIN_W, bool L0>
__global__ void prep_w(const float* __restrict__ w, uint4* __restrict__ out) {
    constexpr int KT16 = KTOT / 16;
    constexpr int MW   = COUT / 32;
    const int total = 9 * KT16 * MW * 2 * 32;
    int idx = blockIdx.x * blockDim.x + threadIdx.x;
    if (idx >= total) return;
    int t = idx;
    const int lane = t & 31; t >>= 5;
    const int mt = t & 1; t >>= 1;
    const int mw = t % MW; t /= MW;
    const int ks = t % KT16;
    const int tap = t / KT16;

    const int co0 = mw * 32 + mt * 16 + (lane >> 2);
    const int kb  = ks * 16 + (lane & 3) * 2;

    auto Wv = [&](int co, int k) -> float {
        int cw;
        if (L0) cw = (k == 0) ? 0 : ((k >= 2 && k < 34) ? k - 1 : -1);
        else    cw = k;
        if (cw < 0) return 0.f;
        return w[((size_t)co * CIN_W + cw) * 9 + tap];
    };
    uint4 o;
    o.x = h2u(Wv(co0,     kb),     Wv(co0,     kb + 1));
    o.y = h2u(Wv(co0 + 8, kb),     Wv(co0 + 8, kb + 1));
    o.z = h2u(Wv(co0,     kb + 8), Wv(co0,     kb + 9));
    o.w = h2u(Wv(co0 + 8, kb + 8), Wv(co0 + 8, kb + 9));
    out[idx] = o;
}

// One ConvGRU half-cell body (fp16 MMA, packed-mirror staging).
template<int COUT, int L, bool GATES>
__device__ __forceinline__ void run_cell(
    int b,
    const float* __restrict__ x, long long x_bs,
    const uint* __restrict__ mirA,   // L1: planes 0..15 (x=h0)
    const uint* __restrict__ mirB,   // L1: planes 16..31 ; L0: planes 1..16
    const uint4* __restrict__ wf,
    const float* __restrict__ bias,
    const float* __restrict__ hstate,
    float* __restrict__ zbuf,
    float* __restrict__ hout,
    uint* __restrict__ outP,
    uint* Xs)
{
    constexpr int NPL2 = (L == 0) ? 24 : 32;
    constexpr int KT16 = (L == 0) ? 3 : 4;
    constexpr int MW   = COUT / 32;
    constexpr int NGRP = (COUT == 64) ? 4 : 8;
    constexpr int RPW  = 8 / NGRP;
    constexpr int N8   = RPW * 4;
    constexpr int MT   = 2;

    const int tid  = threadIdx.x;
    const int lane = tid & 31;
    const int wid  = tid >> 5;
    const int lq   = lane >> 2;
    const int lr   = lane & 3;
    const int nwarp = wid & (NGRP - 1);
    const int mwarp = wid / NGRP;
    const int pyw   = nwarp * RPW;

    const int row0 = blockIdx.y * 8;
    const int col0 = blockIdx.x * 32;

    // ---- Stage: uint4 copy from packed mirrors (zero halo) ----
    for (int i = tid; i < NPL2 * 100; i += 256) {
        const int pl2 = i / 100;
        const int rem = i - pl2 * 100;
        const int yy  = rem / 10;
        const int s   = rem - yy * 10;
        const int gr  = row0 + yy - 1;
        const int gcb = col0 - 4 + s * 4;
        const bool ok = (gr >= 0 && gr < HW && gcb >= 0 && gcb < HW);
        uint4 v = make_uint4(0, 0, 0, 0);
        if (ok) {
            const int pix = gr * HW + gcb;
            if (L == 0) {
                if (pl2 == 0) {
                    const float4 f = *(const float4*)(x + (size_t)b * x_bs + pix);
                    v.x = h2u(f.x, 0.f); v.y = h2u(f.y, 0.f);
                    v.z = h2u(f.z, 0.f); v.w = h2u(f.w, 0.f);
                } else if (pl2 <= 16) {
                    v = *(const uint4*)(mirB + ((size_t)b * 16 + pl2 - 1) * HW2 + pix);
                }
            } else {
                const uint* src = (pl2 < 16)
                    ? mirA + ((size_t)b * 16 + pl2) * HW2
                    : mirB + ((size_t)b * 16 + pl2 - 16) * HW2;
                v = *(const uint4*)(src + pix);
            }
        }
        *(uint4*)(Xs + pl2 * PSTR + yy * RSTR + s * 4) = v;
    }
    __syncthreads();

    float acc[MT][N8][4];
    #pragma unroll
    for (int mt = 0; mt < MT; mt++)
        #pragma unroll
        for (int j = 0; j < N8; j++)
            #pragma unroll
            for (int q = 0; q < 4; q++) acc[mt][j][q] = 0.f;

    // ---- Main loop: 9 taps x KT16 slices ----
    #pragma unroll 1
    for (int tap = 0; tap < 9; tap++) {
        const int dy = tap / 3, dx = tap - dy * 3;
        #pragma unroll
        for (int ks = 0; ks < KT16; ks++) {
            const uint* xb = Xs + (ks * 8 + lr) * PSTR + dy * RSTR + dx + 3 + lq;
            uint bf[N8][2];
            #pragma unroll
            for (int j = 0; j < N8; j++) {
                const uint* p = xb + (pyw + (j >> 2)) * RSTR + (j & 3) * 8;
                bf[j][0] = p[0];
                bf[j][1] = p[4 * PSTR];
            }
            const uint4* wbase = wf + (((tap * KT16 + ks) * MW + mwarp) * 2) * 32 + lane;
            #pragma unroll
            for (int mt = 0; mt < MT; mt++) {
                const uint4 a = __ldg(wbase + mt * 32);
                #pragma unroll
                for (int j = 0; j < N8; j++)
                    mma16(acc[mt][j], a.x, a.y, a.z, a.w, bf[j][0], bf[j][1]);
            }
        }
    }

    // ---- Epilogue ----
    #pragma unroll
    for (int mt = 0; mt < MT; mt++) {
        #pragma unroll
        for (int j = 0; j < N8; j++) {
            const int py = row0 + pyw + (j >> 2);
            const int px = col0 + (j & 3) * 8 + 2 * lr;
            const size_t pix = (size_t)py * HW + px;
            #pragma unroll
            for (int h2 = 0; h2 < 2; h2++) {
                const int cc = mwarp * 32 + mt * 16 + lq + h2 * 8;
                const float bv = __ldg(bias + cc);
                float v0 = acc[mt][j][h2 * 2 + 0] + bv;
                float v1 = acc[mt][j][h2 * 2 + 1] + bv;
                if (GATES) {
                    if (mwarp == 0) {   // r gate -> packed rh mirror
                        const size_t off = ((size_t)b * 32 + cc) * HW2 + pix;
                        const float2 hv = *(const float2*)(hstate + off);
                        const float r0 = sigf(v0) * hv.x;
                        const float r1 = sigf(v1) * hv.y;
                        const float r0p = __shfl_xor_sync(0xffffffffu, r0, 4);
                        const float r1p = __shfl_xor_sync(0xffffffffu, r1, 4);
                        if (!(lq & 1)) {
                            uint2 wv;
                            wv.x = h2u(r0, r0p);
                            wv.y = h2u(r1, r1p);
                            *(uint2*)(outP + ((size_t)b * 16 + (cc >> 1)) * HW2 + pix) = wv;
                        }
                    } else {            // z gate -> fp32 planes
                        const size_t off = ((size_t)b * 32 + cc - 32) * HW2 + pix;
                        *(float2*)(zbuf + off) = make_float2(sigf(v0), sigf(v1));
                    }
                } else {
                    const size_t off = ((size_t)b * 32 + cc) * HW2 + pix;
                    const float2 zv = *(const float2*)(zbuf + off);
                    const float2 hv = *(const float2*)(hstate + off);
                    const float n0 = tanhfast(v0), n1 = tanhfast(v1);
                    const float o0 = hv.x + zv.x * (n0 - hv.x);
                    const float o1 = hv.y + zv.y * (n1 - hv.y);
                    *(float2*)(hout + off) = make_float2(o0, o1);
                    const float o0p = __shfl_xor_sync(0xffffffffu, o0, 4);
                    const float o1p = __shfl_xor_sync(0xffffffffu, o1, 4);
                    if (!(lq & 1)) {
                        uint2 wv;
                        wv.x = h2u(o0, o0p);
                        wv.y = h2u(o1, o1p);
                        *(uint2*)(outP + ((size_t)b * 16 + (cc >> 1)) * HW2 + pix) = wv;
                    }
                }
            }
        }
    }
}

// Merged launch: blocks [0,nL0) run layer0 @ t=s, blocks [nL0,..) run layer1 @ t=s-1.
__global__ __launch_bounds__(256, 2)
void gates_merged(int nL0,
                  const float* __restrict__ x0, long long x_bs,
                  const uint* __restrict__ m0B, const uint4* __restrict__ wf0,
                  const float* __restrict__ b0, const float* __restrict__ h0f,
                  float* __restrict__ z0, uint* __restrict__ rh0,
                  const uint* __restrict__ m1A, const uint* __restrict__ m1B,
                  const uint4* __restrict__ wf1, const float* __restrict__ b1,
                  const float* __restrict__ h1f, float* __restrict__ z1,
                  uint* __restrict__ rh1)
{
    extern __shared__ uint Xs[];
    const int bz = blockIdx.z;
    if (bz < nL0)
        run_cell<64, 0, true>(bz, x0, x_bs, nullptr, m0B, wf0, b0, h0f, z0, nullptr, rh0, Xs);
    else
        run_cell<64, 1, true>(bz - nL0, nullptr, 0, m1A, m1B, wf1, b1, h1f, z1, nullptr, rh1, Xs);
}

__global__ __launch_bounds__(256, 2)
void cand_merged(int nL0,
                 const float* __restrict__ x0, long long x_bs,
                 const uint* __restrict__ rh0, const uint4* __restrict__ wf0,
                 const float* __restrict__ b0, const float* __restrict__ h0f,
                 float* __restrict__ z0, float* __restrict__ hout0, uint* __restrict__ hp0w,
                 const uint* __restrict__ m1A, const uint* __restrict__ rh1,
                 const uint4* __restrict__ wf1, const float* __restrict__ b1,
                 const float* __restrict__ h1f, float* __restrict__ z1,
                 float* __restrict__ hout1, uint* __restrict__ hp1w)
{
    extern __shared__ uint Xs[];
    const int bz = blockIdx.z;
    if (bz < nL0)
        run_cell<32, 0, false>(bz, x0, x_bs, nullptr, rh0, wf0, b0, h0f, z0, hout0, hp0w, Xs);
    else
        run_cell<32, 1, false>(bz - nL0, nullptr, 0, m1A, rh1, wf1, b1, h1f, z1, hout1, hp1w, Xs);
}

extern "C" void kernel_launch(void* const* d_in, const int* in_sizes, int n_in,
                              void* d_out, int out_size)
{
    const float* seq = (const float*)d_in[0];
    const float* gw0 = (const float*)d_in[1];
    const float* gb0 = (const float*)d_in[2];
    const float* cw0 = (const float*)d_in[3];
    const float* cb0 = (const float*)d_in[4];
    const float* gw1 = (const float*)d_in[5];
    const float* gb1 = (const float*)d_in[6];
    const float* cw1 = (const float*)d_in[7];
    const float* cb1 = (const float*)d_in[8];

    float *h0, *h1, *z0, *z1;
    uint *hp0a, *hp0b, *hp1, *rhp0, *rhp1;
    cudaGetSymbolAddress((void**)&h0, g_h0);
    cudaGetSymbolAddress((void**)&h1, g_h1);
    cudaGetSymbolAddress((void**)&z0, g_z0);
    cudaGetSymbolAddress((void**)&z1, g_z1);
    cudaGetSymbolAddress((void**)&hp0a, g_hp0a);
    cudaGetSymbolAddress((void**)&hp0b, g_hp0b);
    cudaGetSymbolAddress((void**)&hp1, g_hp1);
    cudaGetSymbolAddress((void**)&rhp0, g_rhp0);
    cudaGetSymbolAddress((void**)&rhp1, g_rhp1);
    uint4 *wfg0, *wfc0, *wfg1, *wfc1;
    cudaGetSymbolAddress((void**)&wfg0, g_wf_g0);
    cudaGetSymbolAddress((void**)&wfc0, g_wf_c0);
    cudaGetSymbolAddress((void**)&wfg1, g_wf_g1);
    cudaGetSymbolAddress((void**)&wfc1, g_wf_c1);

    const int SM = 32 * PSTR * 4;   // 52224 B (max of both layers)
    cudaFuncSetAttribute(gates_merged, cudaFuncAttributeMaxDynamicSharedMemorySize, SM);
    cudaFuncSetAttribute(cand_merged,  cudaFuncAttributeMaxDynamicSharedMemorySize, SM);

    zero_states_kernel<<<4096, 256>>>();
    prep_w<48, 64, 33, true ><<<(9*3*2*2*32 + 255)/256, 256>>>(gw0, wfg0);
    prep_w<48, 32, 33, true ><<<(9*3*1*2*32 + 255)/256, 256>>>(cw0, wfc0);
    prep_w<64, 64, 64, false><<<(9*4*2*2*32 + 255)/256, 256>>>(gw1, wfg1);
    prep_w<64, 32, 64, false><<<(9*4*1*2*32 + 255)/256, 256>>>(cw1, wfc1);

    dim3 blk(256);
    const long long seq_bs = (long long)NT * HW2;

    // Pipelined steps: step s runs L0(t=s) and L1(t=s-1) concurrently.
    for (int s = 0; s <= NT; s++) {
        const int nL0 = (s < NT) ? NB : 0;
        const int nL1 = (s > 0) ? NB : 0;
        dim3 grid(HW / 32, HW / 8, nL0 + nL1);
        const float* xt = seq + (size_t)s * HW2;
        // h0 mirror double buffer: L0 reads parity (s-1), writes parity s
        const uint* hp0_rd = (s & 1) ? hp0a : hp0b;
        uint*       hp0_wr = (s & 1) ? hp0b : hp0a;

        gates_merged<<<grid, blk, SM>>>(nL0, xt, seq_bs,
            hp0_rd, wfg0, gb0, h0, z0, rhp0,
            hp0_rd, hp1, wfg1, gb1, h1, z1, rhp1);

        float* hout1 = (s == NT) ? (float*)d_out : h1;
        cand_merged<<<grid, blk, SM>>>(nL0, xt, seq_bs,
            rhp0, wfc0, cb0, h0, z0, h0, hp0_wr,
            hp0_rd, rhp1, wfc1, cb1, h1, z1, hout1, hp1);
    }
}

// round 9
// speedup vs baseline: 1.3599x; 1.3599x over previous
#include <cuda_runtime.h>
#include <cuda_fp16.h>
#include <math.h>

#define HW   128
#define HW2  (128*128)
#define NB   8
#define NT   16
#define PSTR 408    // smem plane-pair stride (words)
#define RSTR 40     // smem row stride (words)

typedef unsigned int uint;

// fp32 state (blend precision) + z scratch
__device__ float g_h0[NB*32*HW2];
__device__ float g_h1[NB*32*HW2];
__device__ float g_z [NB*32*HW2];
// packed half2 plane-pair mirrors [b][16][HW2]: (ch 2q, ch 2q+1)
__device__ uint g_hp0[NB*16*HW2];
__device__ uint g_hp1[NB*16*HW2];
__device__ uint g_rhp[NB*16*HW2];

// Pre-swizzled weight fragments (f16x2, m16n8k16 A layout)
__device__ uint4 g_wf_g0[9 * 3 * 2 * 2 * 32];
__device__ uint4 g_wf_c0[9 * 3 * 1 * 2 * 32];
__device__ uint4 g_wf_g1[9 * 4 * 2 * 2 * 32];
__device__ uint4 g_wf_c1[9 * 4 * 1 * 2 * 32];

__global__ void zero_states_kernel() {
    size_t i = (size_t)blockIdx.x * blockDim.x + threadIdx.x;
    float4 z4 = make_float4(0.f, 0.f, 0.f, 0.f);
    ((float4*)g_h0)[i] = z4;
    ((float4*)g_h1)[i] = z4;
    if (i < (size_t)NB*16*HW2/4) {
        uint4 u4 = make_uint4(0, 0, 0, 0);
        ((uint4*)g_hp0)[i] = u4;
        ((uint4*)g_hp1)[i] = u4;
    }
}

__device__ __forceinline__ float sigf(float v) {
    return 1.0f / (1.0f + __expf(-v));
}
__device__ __forceinline__ float tanhfast(float v) {
    return 1.0f - 2.0f / (__expf(2.0f * v) + 1.0f);
}
__device__ __forceinline__ uint h2u(float lo, float hi) {
    __half2 h = __halves2half2(__float2half_rn(lo), __float2half_rn(hi));
    return *(uint*)&h;
}
__device__ __forceinline__ void mma16(float* c, uint a0, uint a1, uint a2, uint a3,
                                      uint b0, uint b1) {
    asm volatile(
        "mma.sync.aligned.m16n8k16.row.col.f32.f16.f16.f32 "
        "{%0,%1,%2,%3},{%4,%5,%6,%7},{%8,%9},{%0,%1,%2,%3};"
        : "+f"(c[0]), "+f"(c[1]), "+f"(c[2]), "+f"(c[3])
        : "r"(a0), "r"(a1), "r"(a2), "r"(a3), "r"(b0), "r"(b1));
}
__device__ __forceinline__ uint smem_u32(const void* p) {
    return (uint)__cvta_generic_to_shared(p);
}
// 16B async copy with zero-fill when pred is false
__device__ __forceinline__ void cp16(uint dst, const void* src, bool pred) {
    int sz = pred ? 16 : 0;
    asm volatile("cp.async.cg.shared.global [%0], [%1], 16, %2;"
                 :: "r"(dst), "l"(src), "r"(sz));
}

// Virtual plane k -> weight cin.
// L0: k==0 -> x (cw 0); 2<=k<34 -> h (cw k-1); else zero-pad.
// L1: k -> k.
template<int KTOT, int COUT, int CIN_W, bool L0>
__global__ void prep_w(const float* __restrict__ w, uint4* __restrict__ out) {
    constexpr int KT16 = KTOT / 16;
    constexpr int MW   = COUT / 32;
    const int total = 9 * KT16 * MW * 2 * 32;
    int idx = blockIdx.x * blockDim.x + threadIdx.x;
    if (idx >= total) return;
    int t = idx;
    const int lane = t & 31; t >>= 5;
    const int mt = t & 1; t >>= 1;
    const int mw = t % MW; t /= MW;
    const int ks = t % KT16;
    const int tap = t / KT16;

    const int co0 = mw * 32 + mt * 16 + (lane >> 2);
    const int kb  = ks * 16 + (lane & 3) * 2;

    auto Wv = [&](int co, int k) -> float {
        int cw;
        if (L0) cw = (k == 0) ? 0 : ((k >= 2 && k < 34) ? k - 1 : -1);
        else    cw = k;
        if (cw < 0) return 0.f;
        return w[((size_t)co * CIN_W + cw) * 9 + tap];
    };
    uint4 o;
    o.x = h2u(Wv(co0,     kb),     Wv(co0,     kb + 1));
    o.y = h2u(Wv(co0 + 8, kb),     Wv(co0 + 8, kb + 1));
    o.z = h2u(Wv(co0,     kb + 8), Wv(co0,     kb + 9));
    o.w = h2u(Wv(co0 + 8, kb + 8), Wv(co0 + 8, kb + 9));
    out[idx] = o;
}

// Implicit-GEMM ConvGRU half-cell, fp16 MMA.
// Warp layout: each warp owns ONE pixel row (32 px = 4 n8-tiles) and ALL couts
// (MT m16-tiles). MT=4 for gates (COUT=64), MT=2 for candidate (COUT=32).
template<int COUT, int L, bool GATES>
__global__ __launch_bounds__(256, 2)
void cell_mma(const float* __restrict__ x, long long x_bs,
              const uint* __restrict__ mirA,   // L1: planes 0..15
              const uint* __restrict__ mirB,   // L1: planes 16..31 ; L0: planes 1..16
              const uint4* __restrict__ wf,
              const float* __restrict__ bias,
              const float* __restrict__ hstate,
              float* __restrict__ zbuf,        // GATES: write ; else read
              float* __restrict__ hout,        // !GATES: fp32 h out
              uint* __restrict__ outP)         // packed out (rh or h mirror)
{
    constexpr int NPL2 = (L == 0) ? 24 : 32;
    constexpr int KT16 = (L == 0) ? 3 : 4;
    constexpr int MT   = COUT / 16;   // 4 (gates) or 2 (cand)
    constexpr int N8   = 4;

    extern __shared__ uint Xs[];     // [NPL2][10][40] half2, plane stride PSTR

    const int tid  = threadIdx.x;
    const int lane = tid & 31;
    const int wid  = tid >> 5;       // 0..7 = pixel row within tile
    const int lq   = lane >> 2;
    const int lr   = lane & 3;

    const int b    = blockIdx.z;
    const int row0 = blockIdx.y * 8;
    const int col0 = blockIdx.x * 32;

    // ---- Stage: cp.async 16B copies with zero-fill halo ----
    for (int i = tid; i < NPL2 * 100; i += 256) {
        const int pl2 = i / 100;
        const int rem = i - pl2 * 100;
        const int yy  = rem / 10;
        const int s   = rem - yy * 10;
        const int gr  = row0 + yy - 1;
        const int gcb = col0 - 4 + s * 4;
        const bool ok = (gr >= 0 && gr < HW && gcb >= 0 && gcb < HW);
        const int pix = ok ? (gr * HW + gcb) : 0;
        uint* dst = Xs + pl2 * PSTR + yy * RSTR + s * 4;
        if (L == 0 && pl2 == 0) {
            // x plane: fp32 -> half2(x,0) conversion (scalar path)
            uint4 v = make_uint4(0, 0, 0, 0);
            if (ok) {
                const float4 f = *(const float4*)(x + (size_t)b * x_bs + pix);
                v.x = h2u(f.x, 0.f); v.y = h2u(f.y, 0.f);
                v.z = h2u(f.z, 0.f); v.w = h2u(f.w, 0.f);
            }
            *(uint4*)dst = v;
        } else if (L == 0 && pl2 > 16) {
            *(uint4*)dst = make_uint4(0, 0, 0, 0);   // zero-pad planes
        } else {
            const uint* src;
            if (L == 0) src = mirB + ((size_t)b * 16 + pl2 - 1) * HW2 + pix;
            else        src = (pl2 < 16)
                            ? mirA + ((size_t)b * 16 + pl2) * HW2 + pix
                            : mirB + ((size_t)b * 16 + pl2 - 16) * HW2 + pix;
            cp16(smem_u32(dst), src, ok);
        }
    }
    asm volatile("cp.async.commit_group;");
    asm volatile("cp.async.wait_group 0;");
    __syncthreads();

    float acc[MT][N8][4];
    #pragma unroll
    for (int mt = 0; mt < MT; mt++)
        #pragma unroll
        for (int j = 0; j < N8; j++)
            #pragma unroll
            for (int q = 0; q < 4; q++) acc[mt][j][q] = 0.f;

    // ---- Main loop: 9 taps x KT16 slices ----
    // Pixel row wid + tap dy -> staged smem row (wid + dy)  [halo -1 baked in]
    #pragma unroll 1
    for (int tap = 0; tap < 9; tap++) {
        const int dy = tap / 3, dx = tap - dy * 3;
        #pragma unroll
        for (int ks = 0; ks < KT16; ks++) {
            const uint* xb = Xs + (ks * 8 + lr) * PSTR + (wid + dy) * RSTR + dx + 3 + lq;
            uint bf[N8][2];
            #pragma unroll
            for (int j = 0; j < N8; j++) {
                bf[j][0] = xb[j * 8];
                bf[j][1] = xb[j * 8 + 4 * PSTR];
            }
            const uint4* wbase = wf + (tap * KT16 + ks) * MT * 32 + lane;
            #pragma unroll
            for (int mt = 0; mt < MT; mt++) {
                const uint4 a = __ldg(wbase + mt * 32);
                #pragma unroll
                for (int j = 0; j < N8; j++)
                    mma16(acc[mt][j], a.x, a.y, a.z, a.w, bf[j][0], bf[j][1]);
            }
        }
    }

    // ---- Epilogue ----
    const int py = row0 + wid;
    #pragma unroll
    for (int mt = 0; mt < MT; mt++) {
        #pragma unroll
        for (int j = 0; j < N8; j++) {
            const int px = col0 + j * 8 + 2 * lr;
            const size_t pix = (size_t)py * HW + px;
            #pragma unroll
            for (int h2 = 0; h2 < 2; h2++) {
                const int cc = mt * 16 + lq + h2 * 8;
                const float bv = __ldg(bias + cc);
                float v0 = acc[mt][j][h2 * 2 + 0] + bv;
                float v1 = acc[mt][j][h2 * 2 + 1] + bv;
                if (GATES) {
                    if (cc < 32) {      // r gate -> packed rh mirror
                        const size_t off = ((size_t)b * 32 + cc) * HW2 + pix;
                        const float2 hv = *(const float2*)(hstate + off);
                        const float r0 = sigf(v0) * hv.x;
                        const float r1 = sigf(v1) * hv.y;
                        const float r0p = __shfl_xor_sync(0xffffffffu, r0, 4);
                        const float r1p = __shfl_xor_sync(0xffffffffu, r1, 4);
                        if (!(lq & 1)) {
                            uint2 wv;
                            wv.x = h2u(r0, r0p);
                            wv.y = h2u(r1, r1p);
                            *(uint2*)(outP + ((size_t)b * 16 + (cc >> 1)) * HW2 + pix) = wv;
                        }
                    } else {            // z gate -> fp32 planes
                        const size_t off = ((size_t)b * 32 + cc - 32) * HW2 + pix;
                        *(float2*)(zbuf + off) = make_float2(sigf(v0), sigf(v1));
                    }
                } else {
                    const size_t off = ((size_t)b * 32 + cc) * HW2 + pix;
                    const float2 zv = *(const float2*)(zbuf + off);
                    const float2 hv = *(const float2*)(hstate + off);
                    const float n0 = tanhfast(v0), n1 = tanhfast(v1);
                    const float o0 = hv.x + zv.x * (n0 - hv.x);
                    const float o1 = hv.y + zv.y * (n1 - hv.y);
                    *(float2*)(hout + off) = make_float2(o0, o1);
                    const float o0p = __shfl_xor_sync(0xffffffffu, o0, 4);
                    const float o1p = __shfl_xor_sync(0xffffffffu, o1, 4);
                    if (!(lq & 1)) {
                        uint2 wv;
                        wv.x = h2u(o0, o0p);
                        wv.y = h2u(o1, o1p);
                        *(uint2*)(outP + ((size_t)b * 16 + (cc >> 1)) * HW2 + pix) = wv;
                    }
                }
            }
        }
    }
}

extern "C" void kernel_launch(void* const* d_in, const int* in_sizes, int n_in,
                              void* d_out, int out_size)
{
    const float* seq = (const float*)d_in[0];
    const float* gw0 = (const float*)d_in[1];
    const float* gb0 = (const float*)d_in[2];
    const float* cw0 = (const float*)d_in[3];
    const float* cb0 = (const float*)d_in[4];
    const float* gw1 = (const float*)d_in[5];
    const float* gb1 = (const float*)d_in[6];
    const float* cw1 = (const float*)d_in[7];
    const float* cb1 = (const float*)d_in[8];

    float *h0, *h1, *zb;
    uint *hp0, *hp1, *rhp;
    cudaGetSymbolAddress((void**)&h0, g_h0);
    cudaGetSymbolAddress((void**)&h1, g_h1);
    cudaGetSymbolAddress((void**)&zb, g_z);
    cudaGetSymbolAddress((void**)&hp0, g_hp0);
    cudaGetSymbolAddress((void**)&hp1, g_hp1);
    cudaGetSymbolAddress((void**)&rhp, g_rhp);
    uint4 *wfg0, *wfc0, *wfg1, *wfc1;
    cudaGetSymbolAddress((void**)&wfg0, g_wf_g0);
    cudaGetSymbolAddress((void**)&wfc0, g_wf_c0);
    cudaGetSymbolAddress((void**)&wfg1, g_wf_g1);
    cudaGetSymbolAddress((void**)&wfc1, g_wf_c1);

    const int SM0 = 24 * PSTR * 4;   // 39168 B
    const int SM1 = 32 * PSTR * 4;   // 52224 B
    cudaFuncSetAttribute(cell_mma<64, 0, true >, cudaFuncAttributeMaxDynamicSharedMemorySize, SM0);
    cudaFuncSetAttribute(cell_mma<32, 0, false>, cudaFuncAttributeMaxDynamicSharedMemorySize, SM0);
    cudaFuncSetAttribute(cell_mma<64, 1, true >, cudaFuncAttributeMaxDynamicSharedMemorySize, SM1);
    cudaFuncSetAttribute(cell_mma<32, 1, false>, cudaFuncAttributeMaxDynamicSharedMemorySize, SM1);

    zero_states_kernel<<<4096, 256>>>();
    prep_w<48, 64, 33, true ><<<(9*3*2*2*32 + 255)/256, 256>>>(gw0, wfg0);
    prep_w<48, 32, 33, true ><<<(9*3*1*2*32 + 255)/256, 256>>>(cw0, wfc0);
    prep_w<64, 64, 64, false><<<(9*4*2*2*32 + 255)/256, 256>>>(gw1, wfg1);
    prep_w<64, 32, 64, false><<<(9*4*1*2*32 + 255)/256, 256>>>(cw1, wfc1);

    dim3 grid(HW / 32, HW / 8, NB);  // (4, 16, 8)
    dim3 blk(256);
    const long long seq_bs = (long long)NT * HW2;

    for (int t = 0; t < NT; t++) {
        const float* xt = seq + (size_t)t * HW2;
        // Layer 0 (x = seq frame, h = h0)
        cell_mma<64, 0, true ><<<grid, blk, SM0>>>(xt, seq_bs, hp0, hp0, wfg0, gb0,
                                                   h0, zb, h0, rhp);
        cell_mma<32, 0, false><<<grid, blk, SM0>>>(xt, seq_bs, rhp, rhp, wfc0, cb0,
                                                   h0, zb, h0, hp0);
        // Layer 1 (x = h0, h = h1)
        cell_mma<64, 1, true ><<<grid, blk, SM1>>>(nullptr, 0, hp0, hp1, wfg1, gb1,
                                                   h1, zb, h1, rhp);
        float* hout = (t == NT - 1) ? (float*)d_out : h1;
        cell_mma<32, 1, false><<<grid, blk, SM1>>>(nullptr, 0, hp0, rhp, wfc1, cb1,
                                                   h1, zb, hout, hp1);
    }
}

// round 10
// speedup vs baseline: 1.5048x; 1.1066x over previous
#include <cuda_runtime.h>
#include <cuda_fp16.h>
#include <math.h>

#define HW   128
#define HW2  (128*128)
#define NB   8
#define NT   16
#define PSTR 408    // smem plane-pair stride (words)
#define RSTR 40     // smem row stride (words)

typedef unsigned int uint;

// fp32 state (blend precision) + per-layer z scratch
__device__ float g_h0[NB*32*HW2];
__device__ float g_h1[NB*32*HW2];
__device__ float g_z0[NB*32*HW2];
__device__ float g_z1[NB*32*HW2];
// packed half2 plane-pair mirrors [b][16][HW2]: (ch 2q, ch 2q+1)
__device__ uint g_hp0a[NB*16*HW2];   // h0 mirror parity 0
__device__ uint g_hp0b[NB*16*HW2];   // h0 mirror parity 1
__device__ uint g_hp1 [NB*16*HW2];
__device__ uint g_rhp0[NB*16*HW2];
__device__ uint g_rhp1[NB*16*HW2];

// Pre-swizzled weight fragments (f16x2, m16n8k16 A layout)
__device__ uint4 g_wf_g0[9 * 3 * 2 * 2 * 32];
__device__ uint4 g_wf_c0[9 * 3 * 1 * 2 * 32];
__device__ uint4 g_wf_g1[9 * 4 * 2 * 2 * 32];
__device__ uint4 g_wf_c1[9 * 4 * 1 * 2 * 32];

__global__ void zero_states_kernel() {
    size_t i = (size_t)blockIdx.x * blockDim.x + threadIdx.x;
    float4 z4 = make_float4(0.f, 0.f, 0.f, 0.f);
    ((float4*)g_h0)[i] = z4;
    ((float4*)g_h1)[i] = z4;
    if (i < (size_t)NB*16*HW2/4) {
        uint4 u4 = make_uint4(0, 0, 0, 0);
        ((uint4*)g_hp0a)[i] = u4;
        ((uint4*)g_hp0b)[i] = u4;
        ((uint4*)g_hp1 )[i] = u4;
    }
}

__device__ __forceinline__ float sigf(float v) {
    return 1.0f / (1.0f + __expf(-v));
}
__device__ __forceinline__ float tanhfast(float v) {
    return 1.0f - 2.0f / (__expf(2.0f * v) + 1.0f);
}
__device__ __forceinline__ uint h2u(float lo, float hi) {
    __half2 h = __halves2half2(__float2half_rn(lo), __float2half_rn(hi));
    return *(uint*)&h;
}
__device__ __forceinline__ void mma16(float* c, uint a0, uint a1, uint a2, uint a3,
                                      uint b0, uint b1) {
    asm volatile(
        "mma.sync.aligned.m16n8k16.row.col.f32.f16.f16.f32 "
        "{%0,%1,%2,%3},{%4,%5,%6,%7},{%8,%9},{%0,%1,%2,%3};"
        : "+f"(c[0]), "+f"(c[1]), "+f"(c[2]), "+f"(c[3])
        : "r"(a0), "r"(a1), "r"(a2), "r"(a3), "r"(b0), "r"(b1));
}
__device__ __forceinline__ uint smem_u32(const void* p) {
    return (uint)__cvta_generic_to_shared(p);
}
// 16B async copy with zero-fill when pred is false
__device__ __forceinline__ void cp16(uint dst, const void* src, bool pred) {
    int sz = pred ? 16 : 0;
    asm volatile("cp.async.cg.shared.global [%0], [%1], 16, %2;"
                 :: "r"(dst), "l"(src), "r"(sz));
}

// Virtual plane k -> weight cin.
// L0: k==0 -> x (cw 0); 2<=k<34 -> h (cw k-1); else zero-pad.
// L1: k -> k.
template<int KTOT, int COUT, int CIN_W, bool L0>
__global__ void prep_w(const float* __restrict__ w, uint4* __restrict__ out) {
    constexpr int KT16 = KTOT / 16;
    constexpr int MW   = COUT / 32;
    const int total = 9 * KT16 * MW * 2 * 32;
    int idx = blockIdx.x * blockDim.x + threadIdx.x;
    if (idx >= total) return;
    int t = idx;
    const int lane = t & 31; t >>= 5;
    const int mt = t & 1; t >>= 1;
    const int mw = t % MW; t /= MW;
    const int ks = t % KT16;
    const int tap = t / KT16;

    const int co0 = mw * 32 + mt * 16 + (lane >> 2);
    const int kb  = ks * 16 + (lane & 3) * 2;

    auto Wv = [&](int co, int k) -> float {
        int cw;
        if (L0) cw = (k == 0) ? 0 : ((k >= 2 && k < 34) ? k - 1 : -1);
        else    cw = k;
        if (cw < 0) return 0.f;
        return w[((size_t)co * CIN_W + cw) * 9 + tap];
    };
    uint4 o;
    o.x = h2u(Wv(co0,     kb),     Wv(co0,     kb + 1));
    o.y = h2u(Wv(co0 + 8, kb),     Wv(co0 + 8, kb + 1));
    o.z = h2u(Wv(co0,     kb + 8), Wv(co0,     kb + 9));
    o.w = h2u(Wv(co0 + 8, kb + 8), Wv(co0 + 8, kb + 9));
    out[idx] = o;
}

// Implicit-GEMM ConvGRU half-cell, fp16 MMA.
// Warp layout: each warp owns ONE pixel row (32 px = 4 n8-tiles) and ALL couts
// (MT m16-tiles). MT=4 for gates (COUT=64), MT=2 for candidate (COUT=32).
template<int COUT, int L, bool GATES>
__global__ __launch_bounds__(256, 2)
void cell_mma(const float* __restrict__ x, long long x_bs,
              const uint* __restrict__ mirA,   // L1: planes 0..15
              const uint* __restrict__ mirB,   // L1: planes 16..31 ; L0: planes 1..16
              const uint4* __restrict__ wf,
              const float* __restrict__ bias,
              const float* __restrict__ hstate,
              float* __restrict__ zbuf,        // GATES: write ; else read
              float* __restrict__ hout,        // !GATES: fp32 h out
              uint* __restrict__ outP)         // packed out (rh or h mirror)
{
    constexpr int NPL2 = (L == 0) ? 24 : 32;
    constexpr int KT16 = (L == 0) ? 3 : 4;
    constexpr int MT   = COUT / 16;   // 4 (gates) or 2 (cand)
    constexpr int N8   = 4;

    extern __shared__ uint Xs[];     // [NPL2][10][40] half2, plane stride PSTR

    const int tid  = threadIdx.x;
    const int lane = tid & 31;
    const int wid  = tid >> 5;       // 0..7 = pixel row within tile
    const int lq   = lane >> 2;
    const int lr   = lane & 3;

    const int b    = blockIdx.z;
    const int row0 = blockIdx.y * 8;
    const int col0 = blockIdx.x * 32;

    // ---- Stage: cp.async 16B copies with zero-fill halo ----
    for (int i = tid; i < NPL2 * 100; i += 256) {
        const int pl2 = i / 100;
        const int rem = i - pl2 * 100;
        const int yy  = rem / 10;
        const int s   = rem - yy * 10;
        const int gr  = row0 + yy - 1;
        const int gcb = col0 - 4 + s * 4;
        const bool ok = (gr >= 0 && gr < HW && gcb >= 0 && gcb < HW);
        const int pix = ok ? (gr * HW + gcb) : 0;
        uint* dst = Xs + pl2 * PSTR + yy * RSTR + s * 4;
        if (L == 0 && pl2 == 0) {
            // x plane: fp32 -> half2(x,0) conversion (scalar path)
            uint4 v = make_uint4(0, 0, 0, 0);
            if (ok) {
                const float4 f = *(const float4*)(x + (size_t)b * x_bs + pix);
                v.x = h2u(f.x, 0.f); v.y = h2u(f.y, 0.f);
                v.z = h2u(f.z, 0.f); v.w = h2u(f.w, 0.f);
            }
            *(uint4*)dst = v;
        } else if (L == 0 && pl2 > 16) {
            *(uint4*)dst = make_uint4(0, 0, 0, 0);   // zero-pad planes
        } else {
            const uint* src;
            if (L == 0) src = mirB + ((size_t)b * 16 + pl2 - 1) * HW2 + pix;
            else        src = (pl2 < 16)
                            ? mirA + ((size_t)b * 16 + pl2) * HW2 + pix
                            : mirB + ((size_t)b * 16 + pl2 - 16) * HW2 + pix;
            cp16(smem_u32(dst), src, ok);
        }
    }
    asm volatile("cp.async.commit_group;");
    asm volatile("cp.async.wait_group 0;");
    __syncthreads();

    float acc[MT][N8][4];
    #pragma unroll
    for (int mt = 0; mt < MT; mt++)
        #pragma unroll
        for (int j = 0; j < N8; j++)
            #pragma unroll
            for (int q = 0; q < 4; q++) acc[mt][j][q] = 0.f;

    // ---- Main loop: 9 taps x KT16 slices ----
    // Pixel row wid + tap dy -> staged smem row (wid + dy)  [halo -1 baked in]
    #pragma unroll 1
    for (int tap = 0; tap < 9; tap++) {
        const int dy = tap / 3, dx = tap - dy * 3;
        #pragma unroll
        for (int ks = 0; ks < KT16; ks++) {
            const uint* xb = Xs + (ks * 8 + lr) * PSTR + (wid + dy) * RSTR + dx + 3 + lq;
            uint bf[N8][2];
            #pragma unroll
            for (int j = 0; j < N8; j++) {
                bf[j][0] = xb[j * 8];
                bf[j][1] = xb[j * 8 + 4 * PSTR];
            }
            const uint4* wbase = wf + (tap * KT16 + ks) * MT * 32 + lane;
            #pragma unroll
            for (int mt = 0; mt < MT; mt++) {
                const uint4 a = __ldg(wbase + mt * 32);
                #pragma unroll
                for (int j = 0; j < N8; j++)
                    mma16(acc[mt][j], a.x, a.y, a.z, a.w, bf[j][0], bf[j][1]);
            }
        }
    }

    // ---- Epilogue ----
    const int py = row0 + wid;
    #pragma unroll
    for (int mt = 0; mt < MT; mt++) {
        #pragma unroll
        for (int j = 0; j < N8; j++) {
            const int px = col0 + j * 8 + 2 * lr;
            const size_t pix = (size_t)py * HW + px;
            #pragma unroll
            for (int h2 = 0; h2 < 2; h2++) {
                const int cc = mt * 16 + lq + h2 * 8;
                const float bv = __ldg(bias + cc);
                float v0 = acc[mt][j][h2 * 2 + 0] + bv;
                float v1 = acc[mt][j][h2 * 2 + 1] + bv;
                if (GATES) {
                    if (cc < 32) {      // r gate -> packed rh mirror
                        const size_t off = ((size_t)b * 32 + cc) * HW2 + pix;
                        const float2 hv = *(const float2*)(hstate + off);
                        const float r0 = sigf(v0) * hv.x;
                        const float r1 = sigf(v1) * hv.y;
                        const float r0p = __shfl_xor_sync(0xffffffffu, r0, 4);
                        const float r1p = __shfl_xor_sync(0xffffffffu, r1, 4);
                        if (!(lq & 1)) {
                            uint2 wv;
                            wv.x = h2u(r0, r0p);
                            wv.y = h2u(r1, r1p);
                            *(uint2*)(outP + ((size_t)b * 16 + (cc >> 1)) * HW2 + pix) = wv;
                        }
                    } else {            // z gate -> fp32 planes
                        const size_t off = ((size_t)b * 32 + cc - 32) * HW2 + pix;
                        *(float2*)(zbuf + off) = make_float2(sigf(v0), sigf(v1));
                    }
                } else {
                    const size_t off = ((size_t)b * 32 + cc) * HW2 + pix;
                    const float2 zv = *(const float2*)(zbuf + off);
                    const float2 hv = *(const float2*)(hstate + off);
                    const float n0 = tanhfast(v0), n1 = tanhfast(v1);
                    const float o0 = hv.x + zv.x * (n0 - hv.x);
                    const float o1 = hv.y + zv.y * (n1 - hv.y);
                    *(float2*)(hout + off) = make_float2(o0, o1);
                    const float o0p = __shfl_xor_sync(0xffffffffu, o0, 4);
                    const float o1p = __shfl_xor_sync(0xffffffffu, o1, 4);
                    if (!(lq & 1)) {
                        uint2 wv;
                        wv.x = h2u(o0, o0p);
                        wv.y = h2u(o1, o1p);
                        *(uint2*)(outP + ((size_t)b * 16 + (cc >> 1)) * HW2 + pix) = wv;
                    }
                }
            }
        }
    }
}

extern "C" void kernel_launch(void* const* d_in, const int* in_sizes, int n_in,
                              void* d_out, int out_size)
{
    const float* seq = (const float*)d_in[0];
    const float* gw0 = (const float*)d_in[1];
    const float* gb0 = (const float*)d_in[2];
    const float* cw0 = (const float*)d_in[3];
    const float* cb0 = (const float*)d_in[4];
    const float* gw1 = (const float*)d_in[5];
    const float* gb1 = (const float*)d_in[6];
    const float* cw1 = (const float*)d_in[7];
    const float* cb1 = (const float*)d_in[8];

    float *h0, *h1, *z0, *z1;
    uint *hp0a, *hp0b, *hp1, *rhp0, *rhp1;
    cudaGetSymbolAddress((void**)&h0, g_h0);
    cudaGetSymbolAddress((void**)&h1, g_h1);
    cudaGetSymbolAddress((void**)&z0, g_z0);
    cudaGetSymbolAddress((void**)&z1, g_z1);
    cudaGetSymbolAddress((void**)&hp0a, g_hp0a);
    cudaGetSymbolAddress((void**)&hp0b, g_hp0b);
    cudaGetSymbolAddress((void**)&hp1, g_hp1);
    cudaGetSymbolAddress((void**)&rhp0, g_rhp0);
    cudaGetSymbolAddress((void**)&rhp1, g_rhp1);
    uint4 *wfg0, *wfc0, *wfg1, *wfc1;
    cudaGetSymbolAddress((void**)&wfg0, g_wf_g0);
    cudaGetSymbolAddress((void**)&wfc0, g_wf_c0);
    cudaGetSymbolAddress((void**)&wfg1, g_wf_g1);
    cudaGetSymbolAddress((void**)&wfc1, g_wf_c1);

    const int SM0 = 24 * PSTR * 4;   // 39168 B
    const int SM1 = 32 * PSTR * 4;   // 52224 B
    cudaFuncSetAttribute(cell_mma<64, 0, true >, cudaFuncAttributeMaxDynamicSharedMemorySize, SM0);
    cudaFuncSetAttribute(cell_mma<32, 0, false>, cudaFuncAttributeMaxDynamicSharedMemorySize, SM0);
    cudaFuncSetAttribute(cell_mma<64, 1, true >, cudaFuncAttributeMaxDynamicSharedMemorySize, SM1);
    cudaFuncSetAttribute(cell_mma<32, 1, false>, cudaFuncAttributeMaxDynamicSharedMemorySize, SM1);

    // One-time stream/event creation (host resources only; no device allocs).
    static cudaStream_t sA = nullptr, sB = nullptr;
    static cudaEvent_t evFork, evL0c[NT], evJoinB;
    if (!sA) {
        cudaStreamCreateWithFlags(&sA, cudaStreamNonBlocking);
        cudaStreamCreateWithFlags(&sB, cudaStreamNonBlocking);
        cudaEventCreateWithFlags(&evFork, cudaEventDisableTiming);
        for (int t = 0; t < NT; t++)
            cudaEventCreateWithFlags(&evL0c[t], cudaEventDisableTiming);
        cudaEventCreateWithFlags(&evJoinB, cudaEventDisableTiming);
    }

    zero_states_kernel<<<4096, 256>>>();
    prep_w<48, 64, 33, true ><<<(9*3*2*2*32 + 255)/256, 256>>>(gw0, wfg0);
    prep_w<48, 32, 33, true ><<<(9*3*1*2*32 + 255)/256, 256>>>(cw0, wfc0);
    prep_w<64, 64, 64, false><<<(9*4*2*2*32 + 255)/256, 256>>>(gw1, wfg1);
    prep_w<64, 32, 64, false><<<(9*4*1*2*32 + 255)/256, 256>>>(cw1, wfc1);

    // Fork both worker streams off the capture-origin (default) stream.
    cudaEventRecord(evFork, 0);
    cudaStreamWaitEvent(sA, evFork, 0);
    cudaStreamWaitEvent(sB, evFork, 0);

    dim3 grid(HW / 32, HW / 8, NB);  // (4, 16, 8)
    dim3 blk(256);
    const long long seq_bs = (long long)NT * HW2;

    for (int t = 0; t < NT; t++) {
        const float* xt = seq + (size_t)t * HW2;
        // h0 mirror parity: L0c(t) writes hp0[t&1]; L0g(t) reads hp0[(t+1)&1]
        const uint* hp0_rd = (t & 1) ? hp0a : hp0b;
        uint*       hp0_wr = (t & 1) ? hp0b : hp0a;

        // ---- Stream A: layer 0, step t ----
        cell_mma<64, 0, true ><<<grid, blk, SM0, sA>>>(xt, seq_bs, hp0_rd, hp0_rd,
                                                       wfg0, gb0, h0, z0, h0, rhp0);
        cell_mma<32, 0, false><<<grid, blk, SM0, sA>>>(xt, seq_bs, rhp0, rhp0,
                                                       wfc0, cb0, h0, z0, h0, hp0_wr);
        cudaEventRecord(evL0c[t], sA);

        // ---- Stream B: layer 1, step t (waits on L0c(t); overlaps L0(t+1)) ----
        cudaStreamWaitEvent(sB, evL0c[t], 0);
        cell_mma<64, 1, true ><<<grid, blk, SM1, sB>>>(nullptr, 0, hp0_wr, hp1,
                                                       wfg1, gb1, h1, z1, h1, rhp1);
        float* hout = (t == NT - 1) ? (float*)d_out : h1;
        cell_mma<32, 1, false><<<grid, blk, SM1, sB>>>(nullptr, 0, hp0_wr, rhp1,
                                                       wfc1, cb1, h1, z1, hout, hp1);
    }

    // Join back to the origin stream (stream B's chain already depends on A's).
    cudaEventRecord(evJoinB, sB);
    cudaStreamWaitEvent(0, evJoinB, 0);
}

// round 11
// speedup vs baseline: 1.5730x; 1.0454x over previous
#include <cuda_runtime.h>
#include <cuda_fp16.h>
#include <math.h>

#define HW   128
#define HW2  (128*128)
#define NB   8
#define NT   16
#define PSTR 408    // smem plane-pair stride (words)
#define RSTR 40     // smem row stride (words)

typedef unsigned int uint;

// fp32 state (blend precision) + per-layer z scratch
__device__ float g_h0[NB*32*HW2];
__device__ float g_h1[NB*32*HW2];
__device__ float g_z0[NB*32*HW2];
__device__ float g_z1[NB*32*HW2];
// packed half2 plane-pair mirrors [b][16][HW2]: (ch 2q, ch 2q+1)
__device__ uint g_hp0a[NB*16*HW2];   // h0 mirror parity 0
__device__ uint g_hp0b[NB*16*HW2];   // h0 mirror parity 1
__device__ uint g_hp1 [NB*16*HW2];
__device__ uint g_rhp0[NB*16*HW2];
__device__ uint g_rhp1[NB*16*HW2];

// Pre-swizzled weight fragments (f16x2, m16n8k16 A layout; L0 slice 2 is k8)
__device__ uint4 g_wf_g0[9 * 3 * 4 * 32];
__device__ uint4 g_wf_c0[9 * 3 * 2 * 32];
__device__ uint4 g_wf_g1[9 * 4 * 4 * 32];
__device__ uint4 g_wf_c1[9 * 4 * 2 * 32];

__global__ void zero_states_kernel() {
    size_t i = (size_t)blockIdx.x * blockDim.x + threadIdx.x;
    float4 z4 = make_float4(0.f, 0.f, 0.f, 0.f);
    ((float4*)g_h0)[i] = z4;
    ((float4*)g_h1)[i] = z4;
    if (i < (size_t)NB*16*HW2/4) {
        uint4 u4 = make_uint4(0, 0, 0, 0);
        ((uint4*)g_hp0a)[i] = u4;
        ((uint4*)g_hp0b)[i] = u4;
        ((uint4*)g_hp1 )[i] = u4;
    }
}

__device__ __forceinline__ float sigf(float v) {
    return 1.0f / (1.0f + __expf(-v));
}
__device__ __forceinline__ float tanhfast(float v) {
    return 1.0f - 2.0f / (__expf(2.0f * v) + 1.0f);
}
__device__ __forceinline__ uint h2u(float lo, float hi) {
    __half2 h = __halves2half2(__float2half_rn(lo), __float2half_rn(hi));
    return *(uint*)&h;
}
__device__ __forceinline__ void mma16(float* c, uint a0, uint a1, uint a2, uint a3,
                                      uint b0, uint b1) {
    asm volatile(
        "mma.sync.aligned.m16n8k16.row.col.f32.f16.f16.f32 "
        "{%0,%1,%2,%3},{%4,%5,%6,%7},{%8,%9},{%0,%1,%2,%3};"
        : "+f"(c[0]), "+f"(c[1]), "+f"(c[2]), "+f"(c[3])
        : "r"(a0), "r"(a1), "r"(a2), "r"(a3), "r"(b0), "r"(b1));
}
__device__ __forceinline__ void mma8(float* c, uint a0, uint a1, uint b0) {
    asm volatile(
        "mma.sync.aligned.m16n8k8.row.col.f32.f16.f16.f32 "
        "{%0,%1,%2,%3},{%4,%5},{%6},{%0,%1,%2,%3};"
        : "+f"(c[0]), "+f"(c[1]), "+f"(c[2]), "+f"(c[3])
        : "r"(a0), "r"(a1), "r"(b0));
}
__device__ __forceinline__ uint smem_u32(const void* p) {
    return (uint)__cvta_generic_to_shared(p);
}
// 16B async copy with zero-fill when pred is false
__device__ __forceinline__ void cp16(uint dst, const void* src, bool pred) {
    int sz = pred ? 16 : 0;
    asm volatile("cp.async.cg.shared.global [%0], [%1], 16, %2;"
                 :: "r"(dst), "l"(src), "r"(sz));
}

// Virtual plane k -> weight cin.
// L0: k==0 -> x (cw 0); 2<=k<34 -> h (cw k-1); else zero-pad.  K=40 (2xK16 + 1xK8)
// L1: k -> k.  K=64 (4xK16)
template<int NSL, int COUT, int CIN_W, bool L0>
__global__ void prep_w(const float* __restrict__ w, uint4* __restrict__ out) {
    constexpr int MT = COUT / 16;
    const int total = 9 * NSL * MT * 32;
    int idx = blockIdx.x * blockDim.x + threadIdx.x;
    if (idx >= total) return;
    int t = idx;
    const int lane = t & 31; t >>= 5;
    const int mt = t % MT; t /= MT;
    const int ks = t % NSL;
    const int tap = t / NSL;

    const int co0 = mt * 16 + (lane >> 2);
    const int kb  = ks * 16 + (lane & 3) * 2;
    const bool k8 = (L0 && ks == 2);   // L0 slice 2: m16n8k8 covering k 32..39

    auto Wv = [&](int co, int k) -> float {
        int cw;
        if (L0) cw = (k == 0) ? 0 : ((k >= 2 && k < 34) ? k - 1 : -1);
        else    cw = k;
        if (cw < 0) return 0.f;
        return w[((size_t)co * CIN_W + cw) * 9 + tap];
    };
    uint4 o;
    o.x = h2u(Wv(co0,     kb),     Wv(co0,     kb + 1));
    o.y = h2u(Wv(co0 + 8, kb),     Wv(co0 + 8, kb + 1));
    o.z = k8 ? 0u : h2u(Wv(co0,     kb + 8), Wv(co0,     kb + 9));
    o.w = k8 ? 0u : h2u(Wv(co0 + 8, kb + 8), Wv(co0 + 8, kb + 9));
    out[idx] = o;
}

// Implicit-GEMM ConvGRU half-cell, fp16 MMA.
// Warp layout: each warp owns ONE pixel row (32 px = 4 n8-tiles) and ALL couts.
template<int COUT, int L, bool GATES>
__global__ __launch_bounds__(256, 2)
void cell_mma(const float* __restrict__ x, long long x_bs,
              const uint* __restrict__ mirA,   // L1: planes 0..15
              const uint* __restrict__ mirB,   // L1: planes 16..31 ; L0: planes 1..16
              const uint4* __restrict__ wf,
              const float* __restrict__ bias,
              const float* __restrict__ hstate,
              float* __restrict__ zbuf,        // GATES: write ; else read
              float* __restrict__ hout,        // !GATES: fp32 h out
              uint* __restrict__ outP)         // packed out (rh or h mirror)
{
    constexpr int NPL2 = (L == 0) ? 20 : 32;   // L0: pairs 0..16 real, 17..19 zero
    constexpr int KT16 = (L == 0) ? 2 : 4;     // full k16 slices
    constexpr int NSL  = (L == 0) ? 3 : 4;     // weight-table slices per tap
    constexpr int MT   = COUT / 16;   // 4 (gates) or 2 (cand)
    constexpr int N8   = 4;

    extern __shared__ uint Xs[];     // [NPL2][10][40] half2, plane stride PSTR

    const int tid  = threadIdx.x;
    const int lane = tid & 31;
    const int wid  = tid >> 5;       // 0..7 = pixel row within tile
    const int lq   = lane >> 2;
    const int lr   = lane & 3;

    const int b    = blockIdx.z;
    const int row0 = blockIdx.y * 8;
    const int col0 = blockIdx.x * 32;

    // ---- Stage: cp.async 16B copies with zero-fill halo ----
    for (int i = tid; i < NPL2 * 100; i += 256) {
        const int pl2 = i / 100;
        const int rem = i - pl2 * 100;
        const int yy  = rem / 10;
        const int s   = rem - yy * 10;
        const int gr  = row0 + yy - 1;
        const int gcb = col0 - 4 + s * 4;
        const bool ok = (gr >= 0 && gr < HW && gcb >= 0 && gcb < HW);
        const int pix = ok ? (gr * HW + gcb) : 0;
        uint* dst = Xs + pl2 * PSTR + yy * RSTR + s * 4;
        if (L == 0 && pl2 == 0) {
            // x plane: fp32 -> half2(x,0) conversion (scalar path)
            uint4 v = make_uint4(0, 0, 0, 0);
            if (ok) {
                const float4 f = *(const float4*)(x + (size_t)b * x_bs + pix);
                v.x = h2u(f.x, 0.f); v.y = h2u(f.y, 0.f);
                v.z = h2u(f.z, 0.f); v.w = h2u(f.w, 0.f);
            }
            *(uint4*)dst = v;
        } else if (L == 0 && pl2 > 16) {
            *(uint4*)dst = make_uint4(0, 0, 0, 0);   // zero-pad pairs 17..19
        } else {
            const uint* src;
            if (L == 0) src = mirB + ((size_t)b * 16 + pl2 - 1) * HW2 + pix;
            else        src = (pl2 < 16)
                            ? mirA + ((size_t)b * 16 + pl2) * HW2 + pix
                            : mirB + ((size_t)b * 16 + pl2 - 16) * HW2 + pix;
            cp16(smem_u32(dst), src, ok);
        }
    }
    asm volatile("cp.async.commit_group;");
    asm volatile("cp.async.wait_group 0;");
    __syncthreads();

    float acc[MT][N8][4];
    #pragma unroll
    for (int mt = 0; mt < MT; mt++)
        #pragma unroll
        for (int j = 0; j < N8; j++)
            #pragma unroll
            for (int q = 0; q < 4; q++) acc[mt][j][q] = 0.f;

    // ---- Main loop: 9 taps x slices ----
    // Pixel row wid + tap dy -> staged smem row (wid + dy)  [halo -1 baked in]
    #pragma unroll (MT == 4 ? 3 : 9)
    for (int tap = 0; tap < 9; tap++) {
        const int dy = tap / 3, dx = tap - dy * 3;
        #pragma unroll
        for (int ks = 0; ks < KT16; ks++) {
            const uint* xb = Xs + (ks * 8 + lr) * PSTR + (wid + dy) * RSTR + dx + 3 + lq;
            uint bf[N8][2];
            #pragma unroll
            for (int j = 0; j < N8; j++) {
                bf[j][0] = xb[j * 8];
                bf[j][1] = xb[j * 8 + 4 * PSTR];
            }
            const uint4* wbase = wf + (tap * NSL + ks) * MT * 32 + lane;
            #pragma unroll
            for (int mt = 0; mt < MT; mt++) {
                const uint4 a = __ldg(wbase + mt * 32);
                #pragma unroll
                for (int j = 0; j < N8; j++)
                    mma16(acc[mt][j], a.x, a.y, a.z, a.w, bf[j][0], bf[j][1]);
            }
        }
        if (L == 0) {
            // K8 tail slice: plane pairs 16..19 (k 32..39)
            const uint* xb = Xs + (16 + lr) * PSTR + (wid + dy) * RSTR + dx + 3 + lq;
            uint bf[N8];
            #pragma unroll
            for (int j = 0; j < N8; j++) bf[j] = xb[j * 8];
            const uint4* wbase = wf + (tap * NSL + 2) * MT * 32 + lane;
            #pragma unroll
            for (int mt = 0; mt < MT; mt++) {
                const uint4 a = __ldg(wbase + mt * 32);
                #pragma unroll
                for (int j = 0; j < N8; j++)
                    mma8(acc[mt][j], a.x, a.y, bf[j]);
            }
        }
    }

    // ---- Epilogue ----
    const int py = row0 + wid;
    #pragma unroll
    for (int mt = 0; mt < MT; mt++) {
        #pragma unroll
        for (int j = 0; j < N8; j++) {
            const int px = col0 + j * 8 + 2 * lr;
            const size_t pix = (size_t)py * HW + px;
            #pragma unroll
            for (int h2 = 0; h2 < 2; h2++) {
                const int cc = mt * 16 + lq + h2 * 8;
                const float bv = __ldg(bias + cc);
                float v0 = acc[mt][j][h2 * 2 + 0] + bv;
                float v1 = acc[mt][j][h2 * 2 + 1] + bv;
                if (GATES) {
                    if (cc < 32) {      // r gate -> packed rh mirror
                        const size_t off = ((size_t)b * 32 + cc) * HW2 + pix;
                        const float2 hv = *(const float2*)(hstate + off);
                        const float r0 = sigf(v0) * hv.x;
                        const float r1 = sigf(v1) * hv.y;
                        const float r0p = __shfl_xor_sync(0xffffffffu, r0, 4);
                        const float r1p = __shfl_xor_sync(0xffffffffu, r1, 4);
                        if (!(lq & 1)) {
                            uint2 wv;
                            wv.x = h2u(r0, r0p);
                            wv.y = h2u(r1, r1p);
                            *(uint2*)(outP + ((size_t)b * 16 + (cc >> 1)) * HW2 + pix) = wv;
                        }
                    } else {            // z gate -> fp32 planes
                        const size_t off = ((size_t)b * 32 + cc - 32) * HW2 + pix;
                        *(float2*)(zbuf + off) = make_float2(sigf(v0), sigf(v1));
                    }
                } else {
                    const size_t off = ((size_t)b * 32 + cc) * HW2 + pix;
                    const float2 zv = *(const float2*)(zbuf + off);
                    const float2 hv = *(const float2*)(hstate + off);
                    const float n0 = tanhfast(v0), n1 = tanhfast(v1);
                    const float o0 = hv.x + zv.x * (n0 - hv.x);
                    const float o1 = hv.y + zv.y * (n1 - hv.y);
                    *(float2*)(hout + off) = make_float2(o0, o1);
                    const float o0p = __shfl_xor_sync(0xffffffffu, o0, 4);
                    const float o1p = __shfl_xor_sync(0xffffffffu, o1, 4);
                    if (!(lq & 1)) {
                        uint2 wv;
                        wv.x = h2u(o0, o0p);
                        wv.y = h2u(o1, o1p);
                        *(uint2*)(outP + ((size_t)b * 16 + (cc >> 1)) * HW2 + pix) = wv;
                    }
                }
            }
        }
    }
}

extern "C" void kernel_launch(void* const* d_in, const int* in_sizes, int n_in,
                              void* d_out, int out_size)
{
    const float* seq = (const float*)d_in[0];
    const float* gw0 = (const float*)d_in[1];
    const float* gb0 = (const float*)d_in[2];
    const float* cw0 = (const float*)d_in[3];
    const float* cb0 = (const float*)d_in[4];
    const float* gw1 = (const float*)d_in[5];
    const float* gb1 = (const float*)d_in[6];
    const float* cw1 = (const float*)d_in[7];
    const float* cb1 = (const float*)d_in[8];

    float *h0, *h1, *z0, *z1;
    uint *hp0a, *hp0b, *hp1, *rhp0, *rhp1;
    cudaGetSymbolAddress((void**)&h0, g_h0);
    cudaGetSymbolAddress((void**)&h1, g_h1);
    cudaGetSymbolAddress((void**)&z0, g_z0);
    cudaGetSymbolAddress((void**)&z1, g_z1);
    cudaGetSymbolAddress((void**)&hp0a, g_hp0a);
    cudaGetSymbolAddress((void**)&hp0b, g_hp0b);
    cudaGetSymbolAddress((void**)&hp1, g_hp1);
    cudaGetSymbolAddress((void**)&rhp0, g_rhp0);
    cudaGetSymbolAddress((void**)&rhp1, g_rhp1);
    uint4 *wfg0, *wfc0, *wfg1, *wfc1;
    cudaGetSymbolAddress((void**)&wfg0, g_wf_g0);
    cudaGetSymbolAddress((void**)&wfc0, g_wf_c0);
    cudaGetSymbolAddress((void**)&wfg1, g_wf_g1);
    cudaGetSymbolAddress((void**)&wfc1, g_wf_c1);

    const int SM0 = 20 * PSTR * 4;   // 32640 B
    const int SM1 = 32 * PSTR * 4;   // 52224 B
    cudaFuncSetAttribute(cell_mma<64, 0, true >, cudaFuncAttributeMaxDynamicSharedMemorySize, SM0);
    cudaFuncSetAttribute(cell_mma<32, 0, false>, cudaFuncAttributeMaxDynamicSharedMemorySize, SM0);
    cudaFuncSetAttribute(cell_mma<64, 1, true >, cudaFuncAttributeMaxDynamicSharedMemorySize, SM1);
    cudaFuncSetAttribute(cell_mma<32, 1, false>, cudaFuncAttributeMaxDynamicSharedMemorySize, SM1);

    // One-time stream/event creation (host resources only; no device allocs).
    static cudaStream_t sA = nullptr, sB = nullptr;
    static cudaEvent_t evFork, evL0c[NT], evJoinB;
    if (!sA) {
        cudaStreamCreateWithFlags(&sA, cudaStreamNonBlocking);
        cudaStreamCreateWithFlags(&sB, cudaStreamNonBlocking);
        cudaEventCreateWithFlags(&evFork, cudaEventDisableTiming);
        for (int t = 0; t < NT; t++)
            cudaEventCreateWithFlags(&evL0c[t], cudaEventDisableTiming);
        cudaEventCreateWithFlags(&evJoinB, cudaEventDisableTiming);
    }

    zero_states_kernel<<<4096, 256>>>();
    prep_w<3, 64, 33, true ><<<(9*3*4*32 + 255)/256, 256>>>(gw0, wfg0);
    prep_w<3, 32, 33, true ><<<(9*3*2*32 + 255)/256, 256>>>(cw0, wfc0);
    prep_w<4, 64, 64, false><<<(9*4*4*32 + 255)/256, 256>>>(gw1, wfg1);
    prep_w<4, 32, 64, false><<<(9*4*2*32 + 255)/256, 256>>>(cw1, wfc1);

    // Fork both worker streams off the capture-origin (default) stream.
    cudaEventRecord(evFork, 0);
    cudaStreamWaitEvent(sA, evFork, 0);
    cudaStreamWaitEvent(sB, evFork, 0);

    dim3 grid(HW / 32, HW / 8, NB);  // (4, 16, 8)
    dim3 blk(256);
    const long long seq_bs = (long long)NT * HW2;

    for (int t = 0; t < NT; t++) {
        const float* xt = seq + (size_t)t * HW2;
        // h0 mirror parity: L0c(t) writes hp0[t&1]; L0g(t) reads hp0[(t+1)&1]
        const uint* hp0_rd = (t & 1) ? hp0a : hp0b;
        uint*       hp0_wr = (t & 1) ? hp0b : hp0a;

        // ---- Stream A: layer 0, step t ----
        cell_mma<64, 0, true ><<<grid, blk, SM0, sA>>>(xt, seq_bs, hp0_rd, hp0_rd,
                                                       wfg0, gb0, h0, z0, h0, rhp0);
        cell_mma<32, 0, false><<<grid, blk, SM0, sA>>>(xt, seq_bs, rhp0, rhp0,
                                                       wfc0, cb0, h0, z0, h0, hp0_wr);
        cudaEventRecord(evL0c[t], sA);

        // ---- Stream B: layer 1, step t (waits on L0c(t); overlaps L0(t+1)) ----
        cudaStreamWaitEvent(sB, evL0c[t], 0);
        cell_mma<64, 1, true ><<<grid, blk, SM1, sB>>>(nullptr, 0, hp0_wr, hp1,
                                                       wfg1, gb1, h1, z1, h1, rhp1);
        float* hout = (t == NT - 1) ? (float*)d_out : h1;
        cell_mma<32, 1, false><<<grid, blk, SM1, sB>>>(nullptr, 0, hp0_wr, rhp1,
                                                       wfc1, cb1, h1, z1, hout, hp1);
    }

    // Join back to the origin stream (stream B's chain already depends on A's).
    cudaEventRecord(evJoinB, sB);
    cudaStreamWaitEvent(0, evJoinB, 0);
}

// round 12
// speedup vs baseline: 1.6427x; 1.0443x over previous
#include <cuda_runtime.h>
#include <cuda_fp16.h>
#include <math.h>

#define HW   128
#define HW2  (128*128)
#define NB   8
#define NT   16
#define PSTR 408    // smem plane-pair stride (words)
#define RSTR 40     // smem row stride (words)

typedef unsigned int uint;

// fp32 state (blend precision) + per-layer z scratch
__device__ float g_h0[NB*32*HW2];
__device__ float g_h1[NB*32*HW2];
__device__ float g_z0[NB*32*HW2];
__device__ float g_z1[NB*32*HW2];
// packed half2 plane-pair mirrors [b][16][HW2]: (ch 2q, ch 2q+1)
__device__ uint g_hp0a[NB*16*HW2];   // h0 mirror parity 0
__device__ uint g_hp0b[NB*16*HW2];   // h0 mirror parity 1
__device__ uint g_hp1 [NB*16*HW2];
__device__ uint g_rhp0[NB*16*HW2];
__device__ uint g_rhp1[NB*16*HW2];

// Pre-swizzled weight fragments (f16x2, m16n8k16 A layout; L0 slice 2 is k8)
__device__ uint4 g_wf_g0[9 * 3 * 4 * 32];
__device__ uint4 g_wf_c0[9 * 3 * 2 * 32];
__device__ uint4 g_wf_g1[9 * 4 * 4 * 32];
__device__ uint4 g_wf_c1[9 * 4 * 2 * 32];

__global__ void zero_states_kernel() {
    size_t i = (size_t)blockIdx.x * blockDim.x + threadIdx.x;
    float4 z4 = make_float4(0.f, 0.f, 0.f, 0.f);
    ((float4*)g_h0)[i] = z4;
    ((float4*)g_h1)[i] = z4;
    if (i < (size_t)NB*16*HW2/4) {
        uint4 u4 = make_uint4(0, 0, 0, 0);
        ((uint4*)g_hp0a)[i] = u4;
        ((uint4*)g_hp0b)[i] = u4;
        ((uint4*)g_hp1 )[i] = u4;
    }
}

__device__ __forceinline__ float sigf(float v) {
    return 1.0f / (1.0f + __expf(-v));
}
__device__ __forceinline__ float tanhfast(float v) {
    return 1.0f - 2.0f / (__expf(2.0f * v) + 1.0f);
}
__device__ __forceinline__ uint h2u(float lo, float hi) {
    __half2 h = __halves2half2(__float2half_rn(lo), __float2half_rn(hi));
    return *(uint*)&h;
}
__device__ __forceinline__ void mma16(float* c, uint a0, uint a1, uint a2, uint a3,
                                      uint b0, uint b1) {
    asm volatile(
        "mma.sync.aligned.m16n8k16.row.col.f32.f16.f16.f32 "
        "{%0,%1,%2,%3},{%4,%5,%6,%7},{%8,%9},{%0,%1,%2,%3};"
        : "+f"(c[0]), "+f"(c[1]), "+f"(c[2]), "+f"(c[3])
        : "r"(a0), "r"(a1), "r"(a2), "r"(a3), "r"(b0), "r"(b1));
}
__device__ __forceinline__ void mma8(float* c, uint a0, uint a1, uint b0) {
    asm volatile(
        "mma.sync.aligned.m16n8k8.row.col.f32.f16.f16.f32 "
        "{%0,%1,%2,%3},{%4,%5},{%6},{%0,%1,%2,%3};"
        : "+f"(c[0]), "+f"(c[1]), "+f"(c[2]), "+f"(c[3])
        : "r"(a0), "r"(a1), "r"(b0));
}
__device__ __forceinline__ uint smem_u32(const void* p) {
    return (uint)__cvta_generic_to_shared(p);
}
// 16B async copy with zero-fill when pred is false
__device__ __forceinline__ void cp16(uint dst, const void* src, bool pred) {
    int sz = pred ? 16 : 0;
    asm volatile("cp.async.cg.shared.global [%0], [%1], 16, %2;"
                 :: "r"(dst), "l"(src), "r"(sz));
}

// Merged weight-fragment prep: blockIdx.y selects the table.
// Jobs: 0 = g0 (NSL3, COUT64, CIN33, L0), 1 = c0 (NSL3, 32, 33, L0),
//       2 = g1 (NSL4, 64, 64),            3 = c1 (NSL4, 32, 64)
__global__ void prep_all(const float* __restrict__ gw0, const float* __restrict__ cw0,
                         const float* __restrict__ gw1, const float* __restrict__ cw1,
                         uint4* __restrict__ og0, uint4* __restrict__ oc0,
                         uint4* __restrict__ og1, uint4* __restrict__ oc1)
{
    const int job = blockIdx.y;
    const int NSL   = (job < 2) ? 3 : 4;
    const int MT    = (job & 1) ? 2 : 4;
    const int CIN_W = (job < 2) ? 33 : 64;
    const bool L0   = (job < 2);
    const float* w  = (job == 0) ? gw0 : (job == 1) ? cw0 : (job == 2) ? gw1 : cw1;
    uint4* out      = (job == 0) ? og0 : (job == 1) ? oc0 : (job == 2) ? og1 : oc1;

    const int total = 9 * NSL * MT * 32;
    int idx = blockIdx.x * blockDim.x + threadIdx.x;
    if (idx >= total) return;
    int t = idx;
    const int lane = t & 31; t >>= 5;
    const int mt = t % MT; t /= MT;
    const int ks = t % NSL;
    const int tap = t / NSL;

    const int co0 = mt * 16 + (lane >> 2);
    const int kb  = ks * 16 + (lane & 3) * 2;
    const bool k8 = (L0 && ks == 2);   // L0 slice 2: m16n8k8 covering k 32..39

    auto Wv = [&](int co, int k) -> float {
        int cw;
        if (L0) cw = (k == 0) ? 0 : ((k >= 2 && k < 34) ? k - 1 : -1);
        else    cw = k;
        if (cw < 0) return 0.f;
        return w[((size_t)co * CIN_W + cw) * 9 + tap];
    };
    uint4 o;
    o.x = h2u(Wv(co0,     kb),     Wv(co0,     kb + 1));
    o.y = h2u(Wv(co0 + 8, kb),     Wv(co0 + 8, kb + 1));
    o.z = k8 ? 0u : h2u(Wv(co0,     kb + 8), Wv(co0,     kb + 9));
    o.w = k8 ? 0u : h2u(Wv(co0 + 8, kb + 8), Wv(co0 + 8, kb + 9));
    out[idx] = o;
}

// Implicit-GEMM ConvGRU half-cell, fp16 MMA, two-phase staged pipeline.
template<int COUT, int L, bool GATES>
__global__ __launch_bounds__(256, 2)
void cell_mma(const float* __restrict__ x, long long x_bs,
              const uint* __restrict__ mirA,   // L1: planes 0..15
              const uint* __restrict__ mirB,   // L1: planes 16..31 ; L0: planes 1..16
              const uint4* __restrict__ wf,
              const float* __restrict__ bias,
              const float* __restrict__ hstate,
              float* __restrict__ zbuf,        // GATES: write ; else read
              float* __restrict__ hout,        // !GATES: fp32 h out
              uint* __restrict__ outP)         // packed out (rh or h mirror)
{
    constexpr int NPL2 = (L == 0) ? 20 : 32;   // L0: pairs 0..16 real, 17..19 zero
    constexpr int KT16 = (L == 0) ? 2 : 4;     // full k16 slices
    constexpr int NSL  = (L == 0) ? 3 : 4;     // weight-table slices per tap
    constexpr int MT   = COUT / 16;   // 4 (gates) or 2 (cand)
    constexpr int N8   = 4;

    extern __shared__ uint Xs[];     // [NPL2][10][40] half2, plane stride PSTR

    const int tid  = threadIdx.x;
    const int lane = tid & 31;
    const int wid  = tid >> 5;       // 0..7 = pixel row within tile
    const int lq   = lane >> 2;
    const int lr   = lane & 3;

    const int b    = blockIdx.z;
    const int row0 = blockIdx.y * 8;
    const int col0 = blockIdx.x * 32;

    // ---- Stage (two cp.async groups: A = pairs 0..7, B = rest) ----
    auto stage = [&](int plLo, int plHi) {
        const int cnt = (plHi - plLo) * 100;
        for (int i = tid; i < cnt; i += 256) {
            const int pl2 = plLo + i / 100;
            const int rem = i % 100;
            const int yy  = rem / 10;
            const int s   = rem - yy * 10;
            const int gr  = row0 + yy - 1;
            const int gcb = col0 - 4 + s * 4;
            const bool ok = (gr >= 0 && gr < HW && gcb >= 0 && gcb < HW);
            const int pix = ok ? (gr * HW + gcb) : 0;
            uint* dst = Xs + pl2 * PSTR + yy * RSTR + s * 4;
            if (L == 0 && pl2 == 0) {
                uint4 v = make_uint4(0, 0, 0, 0);
                if (ok) {
                    const float4 f = *(const float4*)(x + (size_t)b * x_bs + pix);
                    v.x = h2u(f.x, 0.f); v.y = h2u(f.y, 0.f);
                    v.z = h2u(f.z, 0.f); v.w = h2u(f.w, 0.f);
                }
                *(uint4*)dst = v;
            } else if (L == 0 && pl2 > 16) {
                *(uint4*)dst = make_uint4(0, 0, 0, 0);
            } else {
                const uint* src;
                if (L == 0) src = mirB + ((size_t)b * 16 + pl2 - 1) * HW2 + pix;
                else        src = (pl2 < 16)
                                ? mirA + ((size_t)b * 16 + pl2) * HW2 + pix
                                : mirB + ((size_t)b * 16 + pl2 - 16) * HW2 + pix;
                cp16(smem_u32(dst), src, ok);
            }
        }
    };
    stage(0, 8);
    asm volatile("cp.async.commit_group;");
    stage(8, NPL2);
    asm volatile("cp.async.commit_group;");

    float acc[MT][N8][4];
    #pragma unroll
    for (int mt = 0; mt < MT; mt++)
        #pragma unroll
        for (int j = 0; j < N8; j++)
            #pragma unroll
            for (int q = 0; q < 4; q++) acc[mt][j][q] = 0.f;

    // Slice compute: taps inner, ks fixed.  Pixel row wid + dy -> smem row (wid+dy).
    auto compute_k16 = [&](int ks) {
        #pragma unroll (MT == 4 ? 3 : 9)
        for (int tap = 0; tap < 9; tap++) {
            const int dy = tap / 3, dx = tap - dy * 3;
            const uint* xb = Xs + (ks * 8 + lr) * PSTR + (wid + dy) * RSTR + dx + 3 + lq;
            uint bf[N8][2];
            #pragma unroll
            for (int j = 0; j < N8; j++) {
                bf[j][0] = xb[j * 8];
                bf[j][1] = xb[j * 8 + 4 * PSTR];
            }
            const uint4* wbase = wf + (tap * NSL + ks) * MT * 32 + lane;
            #pragma unroll
            for (int mt = 0; mt < MT; mt++) {
                const uint4 a = __ldg(wbase + mt * 32);
                #pragma unroll
                for (int j = 0; j < N8; j++)
                    mma16(acc[mt][j], a.x, a.y, a.z, a.w, bf[j][0], bf[j][1]);
            }
        }
    };

    // ---- Phase A: slice 0 while group B still streams ----
    asm volatile("cp.async.wait_group 1;");
    __syncthreads();
    compute_k16(0);

    // ---- Phase B: remaining slices ----
    asm volatile("cp.async.wait_group 0;");
    __syncthreads();
    #pragma unroll
    for (int ks = 1; ks < KT16; ks++) compute_k16(ks);

    if (L == 0) {
        // K8 tail slice: plane pairs 16..19 (k 32..39)
        #pragma unroll (MT == 4 ? 3 : 9)
        for (int tap = 0; tap < 9; tap++) {
            const int dy = tap / 3, dx = tap - dy * 3;
            const uint* xb = Xs + (16 + lr) * PSTR + (wid + dy) * RSTR + dx + 3 + lq;
            uint bf[N8];
            #pragma unroll
            for (int j = 0; j < N8; j++) bf[j] = xb[j * 8];
            const uint4* wbase = wf + (tap * NSL + 2) * MT * 32 + lane;
            #pragma unroll
            for (int mt = 0; mt < MT; mt++) {
                const uint4 a = __ldg(wbase + mt * 32);
                #pragma unroll
                for (int j = 0; j < N8; j++)
                    mma8(acc[mt][j], a.x, a.y, bf[j]);
            }
        }
    }

    // ---- Epilogue ----
    const int py = row0 + wid;
    #pragma unroll
    for (int mt = 0; mt < MT; mt++) {
        #pragma unroll
        for (int j = 0; j < N8; j++) {
            const int px = col0 + j * 8 + 2 * lr;
            const size_t pix = (size_t)py * HW + px;
            #pragma unroll
            for (int h2 = 0; h2 < 2; h2++) {
                const int cc = mt * 16 + lq + h2 * 8;
                const float bv = __ldg(bias + cc);
                float v0 = acc[mt][j][h2 * 2 + 0] + bv;
                float v1 = acc[mt][j][h2 * 2 + 1] + bv;
                if (GATES) {
                    if (cc < 32) {      // r gate -> packed rh mirror (h from smem)
                        const int slot = ((L == 0) ? 1 : 16) + (cc >> 1);
                        const uint w0 = Xs[slot * PSTR + (wid + 1) * RSTR + (j * 8 + 2 * lr + 4)];
                        const uint w1 = Xs[slot * PSTR + (wid + 1) * RSTR + (j * 8 + 2 * lr + 5)];
                        const __half2 h20 = *(const __half2*)&w0;
                        const __half2 h21 = *(const __half2*)&w1;
                        const float hx0 = __half2float((cc & 1) ? h20.y : h20.x);
                        const float hx1 = __half2float((cc & 1) ? h21.y : h21.x);
                        const float r0 = sigf(v0) * hx0;
                        const float r1 = sigf(v1) * hx1;
                        const float r0p = __shfl_xor_sync(0xffffffffu, r0, 4);
                        const float r1p = __shfl_xor_sync(0xffffffffu, r1, 4);
                        if (!(lq & 1)) {
                            uint2 wv;
                            wv.x = h2u(r0, r0p);
                            wv.y = h2u(r1, r1p);
                            *(uint2*)(outP + ((size_t)b * 16 + (cc >> 1)) * HW2 + pix) = wv;
                        }
                    } else {            // z gate -> fp32 planes
                        const size_t off = ((size_t)b * 32 + cc - 32) * HW2 + pix;
                        *(float2*)(zbuf + off) = make_float2(sigf(v0), sigf(v1));
                    }
                } else {
                    const size_t off = ((size_t)b * 32 + cc) * HW2 + pix;
                    const float2 zv = *(const float2*)(zbuf + off);
                    const float2 hv = *(const float2*)(hstate + off);
                    const float n0 = tanhfast(v0), n1 = tanhfast(v1);
                    const float o0 = hv.x + zv.x * (n0 - hv.x);
                    const float o1 = hv.y + zv.y * (n1 - hv.y);
                    *(float2*)(hout + off) = make_float2(o0, o1);
                    const float o0p = __shfl_xor_sync(0xffffffffu, o0, 4);
                    const float o1p = __shfl_xor_sync(0xffffffffu, o1, 4);
                    if (!(lq & 1)) {
                        uint2 wv;
                        wv.x = h2u(o0, o0p);
                        wv.y = h2u(o1, o1p);
                        *(uint2*)(outP + ((size_t)b * 16 + (cc >> 1)) * HW2 + pix) = wv;
                    }
                }
            }
        }
    }
}

extern "C" void kernel_launch(void* const* d_in, const int* in_sizes, int n_in,
                              void* d_out, int out_size)
{
    const float* seq = (const float*)d_in[0];
    const float* gw0 = (const float*)d_in[1];
    const float* gb0 = (const float*)d_in[2];
    const float* cw0 = (const float*)d_in[3];
    const float* cb0 = (const float*)d_in[4];
    const float* gw1 = (const float*)d_in[5];
    const float* gb1 = (const float*)d_in[6];
    const float* cw1 = (const float*)d_in[7];
    const float* cb1 = (const float*)d_in[8];

    float *h0, *h1, *z0, *z1;
    uint *hp0a, *hp0b, *hp1, *rhp0, *rhp1;
    cudaGetSymbolAddress((void**)&h0, g_h0);
    cudaGetSymbolAddress((void**)&h1, g_h1);
    cudaGetSymbolAddress((void**)&z0, g_z0);
    cudaGetSymbolAddress((void**)&z1, g_z1);
    cudaGetSymbolAddress((void**)&hp0a, g_hp0a);
    cudaGetSymbolAddress((void**)&hp0b, g_hp0b);
    cudaGetSymbolAddress((void**)&hp1, g_hp1);
    cudaGetSymbolAddress((void**)&rhp0, g_rhp0);
    cudaGetSymbolAddress((void**)&rhp1, g_rhp1);
    uint4 *wfg0, *wfc0, *wfg1, *wfc1;
    cudaGetSymbolAddress((void**)&wfg0, g_wf_g0);
    cudaGetSymbolAddress((void**)&wfc0, g_wf_c0);
    cudaGetSymbolAddress((void**)&wfg1, g_wf_g1);
    cudaGetSymbolAddress((void**)&wfc1, g_wf_c1);

    const int SM0 = 20 * PSTR * 4;   // 32640 B
    const int SM1 = 32 * PSTR * 4;   // 52224 B
    cudaFuncSetAttribute(cell_mma<64, 0, true >, cudaFuncAttributeMaxDynamicSharedMemorySize, SM0);
    cudaFuncSetAttribute(cell_mma<32, 0, false>, cudaFuncAttributeMaxDynamicSharedMemorySize, SM0);
    cudaFuncSetAttribute(cell_mma<64, 1, true >, cudaFuncAttributeMaxDynamicSharedMemorySize, SM1);
    cudaFuncSetAttribute(cell_mma<32, 1, false>, cudaFuncAttributeMaxDynamicSharedMemorySize, SM1);

    // One-time stream/event creation (host resources only; no device allocs).
    static cudaStream_t sA = nullptr, sB = nullptr;
    static cudaEvent_t evFork, evL0c[NT], evJoinB;
    if (!sA) {
        cudaStreamCreateWithFlags(&sA, cudaStreamNonBlocking);
        cudaStreamCreateWithFlags(&sB, cudaStreamNonBlocking);
        cudaEventCreateWithFlags(&evFork, cudaEventDisableTiming);
        for (int t = 0; t < NT; t++)
            cudaEventCreateWithFlags(&evL0c[t], cudaEventDisableTiming);
        cudaEventCreateWithFlags(&evJoinB, cudaEventDisableTiming);
    }

    zero_states_kernel<<<4096, 256>>>();
    prep_all<<<dim3(18, 4), 256>>>(gw0, cw0, gw1, cw1, wfg0, wfc0, wfg1, wfc1);

    // Fork both worker streams off the capture-origin (default) stream.
    cudaEventRecord(evFork, 0);
    cudaStreamWaitEvent(sA, evFork, 0);
    cudaStreamWaitEvent(sB, evFork, 0);

    dim3 grid(HW / 32, HW / 8, NB);  // (4, 16, 8)
    dim3 blk(256);
    const long long seq_bs = (long long)NT * HW2;

    for (int t = 0; t < NT; t++) {
        const float* xt = seq + (size_t)t * HW2;
        // h0 mirror parity: L0c(t) writes hp0[t&1]; L0g(t) reads hp0[(t+1)&1]
        const uint* hp0_rd = (t & 1) ? hp0a : hp0b;
        uint*       hp0_wr = (t & 1) ? hp0b : hp0a;

        // ---- Stream A: layer 0, step t ----
        cell_mma<64, 0, true ><<<grid, blk, SM0, sA>>>(xt, seq_bs, hp0_rd, hp0_rd,
                                                       wfg0, gb0, h0, z0, h0, rhp0);
        cell_mma<32, 0, false><<<grid, blk, SM0, sA>>>(xt, seq_bs, rhp0, rhp0,
                                                       wfc0, cb0, h0, z0, h0, hp0_wr);
        cudaEventRecord(evL0c[t], sA);

        // ---- Stream B: layer 1, step t (waits on L0c(t); overlaps L0(t+1)) ----
        cudaStreamWaitEvent(sB, evL0c[t], 0);
        cell_mma<64, 1, true ><<<grid, blk, SM1, sB>>>(nullptr, 0, hp0_wr, hp1,
                                                       wfg1, gb1, h1, z1, h1, rhp1);
        float* hout = (t == NT - 1) ? (float*)d_out : h1;
        cell_mma<32, 1, false><<<grid, blk, SM1, sB>>>(nullptr, 0, hp0_wr, rhp1,
                                                       wfc1, cb1, h1, z1, hout, hp1);
    }

    // Join back to the origin stream (stream B's chain already depends on A's).
    cudaEventRecord(evJoinB, sB);
    cudaStreamWaitEvent(0, evJoinB, 0);
}

// round 13
// speedup vs baseline: 1.8251x; 1.1110x over previous
#include <cuda_runtime.h>
#include <cuda_fp16.h>
#include <math.h>

#define HW   128
#define HW2  (128*128)
#define NB   8
#define NT   16
#define PSTR 408    // smem plane-pair stride (words)
#define RSTR 40     // smem row stride (words)

typedef unsigned int uint;

// ALL state/scratch packed half2 plane-pairs [b][16][HW2]: (ch 2q, ch 2q+1)
__device__ uint g_hp0a[NB*16*HW2];   // h0 mirror parity 0
__device__ uint g_hp0b[NB*16*HW2];   // h0 mirror parity 1
__device__ uint g_hp1 [NB*16*HW2];   // h1 mirror
__device__ uint g_rhp0[NB*16*HW2];   // rh scratch layer0
__device__ uint g_rhp1[NB*16*HW2];   // rh scratch layer1
__device__ uint g_zp0 [NB*16*HW2];   // z scratch layer0 (packed half2)
__device__ uint g_zp1 [NB*16*HW2];   // z scratch layer1

// Pre-swizzled weight fragments (f16x2, m16n8k16 A layout; L0 slice 2 is k8)
__device__ uint4 g_wf_g0[9 * 3 * 4 * 32];
__device__ uint4 g_wf_c0[9 * 3 * 2 * 32];
__device__ uint4 g_wf_g1[9 * 4 * 4 * 32];
__device__ uint4 g_wf_c1[9 * 4 * 2 * 32];

__global__ void zero_states_kernel() {     // 524288 threads x uint4
    size_t i = (size_t)blockIdx.x * blockDim.x + threadIdx.x;
    uint4 u4 = make_uint4(0, 0, 0, 0);
    ((uint4*)g_hp0a)[i] = u4;
    ((uint4*)g_hp0b)[i] = u4;
    ((uint4*)g_hp1 )[i] = u4;
}

__device__ __forceinline__ float sigf(float v) {
    return 1.0f / (1.0f + __expf(-v));
}
__device__ __forceinline__ float tanhfast(float v) {
    return 1.0f - 2.0f / (__expf(2.0f * v) + 1.0f);
}
__device__ __forceinline__ uint h2u(float lo, float hi) {
    __half2 h = __halves2half2(__float2half_rn(lo), __float2half_rn(hi));
    return *(uint*)&h;
}
__device__ __forceinline__ void mma16(float* c, uint a0, uint a1, uint a2, uint a3,
                                      uint b0, uint b1) {
    asm volatile(
        "mma.sync.aligned.m16n8k16.row.col.f32.f16.f16.f32 "
        "{%0,%1,%2,%3},{%4,%5,%6,%7},{%8,%9},{%0,%1,%2,%3};"
        : "+f"(c[0]), "+f"(c[1]), "+f"(c[2]), "+f"(c[3])
        : "r"(a0), "r"(a1), "r"(a2), "r"(a3), "r"(b0), "r"(b1));
}
__device__ __forceinline__ void mma8(float* c, uint a0, uint a1, uint b0) {
    asm volatile(
        "mma.sync.aligned.m16n8k8.row.col.f32.f16.f16.f32 "
        "{%0,%1,%2,%3},{%4,%5},{%6},{%0,%1,%2,%3};"
        : "+f"(c[0]), "+f"(c[1]), "+f"(c[2]), "+f"(c[3])
        : "r"(a0), "r"(a1), "r"(b0));
}
__device__ __forceinline__ uint smem_u32(const void* p) {
    return (uint)__cvta_generic_to_shared(p);
}
// 16B async copy with zero-fill when pred is false
__device__ __forceinline__ void cp16(uint dst, const void* src, bool pred) {
    int sz = pred ? 16 : 0;
    asm volatile("cp.async.cg.shared.global [%0], [%1], 16, %2;"
                 :: "r"(dst), "l"(src), "r"(sz));
}

// Merged weight-fragment prep (4 jobs via blockIdx.y).
__global__ void prep_all(const float* __restrict__ gw0, const float* __restrict__ cw0,
                         const float* __restrict__ gw1, const float* __restrict__ cw1,
                         uint4* __restrict__ og0, uint4* __restrict__ oc0,
                         uint4* __restrict__ og1, uint4* __restrict__ oc1)
{
    const int job = blockIdx.y;
    const int NSL   = (job < 2) ? 3 : 4;
    const int MT    = (job & 1) ? 2 : 4;
    const int CIN_W = (job < 2) ? 33 : 64;
    const bool L0   = (job < 2);
    const float* w  = (job == 0) ? gw0 : (job == 1) ? cw0 : (job == 2) ? gw1 : cw1;
    uint4* out      = (job == 0) ? og0 : (job == 1) ? oc0 : (job == 2) ? og1 : oc1;

    const int total = 9 * NSL * MT * 32;
    int idx = blockIdx.x * blockDim.x + threadIdx.x;
    if (idx >= total) return;
    int t = idx;
    const int lane = t & 31; t >>= 5;
    const int mt = t % MT; t /= MT;
    const int ks = t % NSL;
    const int tap = t / NSL;

    const int co0 = mt * 16 + (lane >> 2);
    const int kb  = ks * 16 + (lane & 3) * 2;
    const bool k8 = (L0 && ks == 2);

    auto Wv = [&](int co, int k) -> float {
        int cw;
        if (L0) cw = (k == 0) ? 0 : ((k >= 2 && k < 34) ? k - 1 : -1);
        else    cw = k;
        if (cw < 0) return 0.f;
        return w[((size_t)co * CIN_W + cw) * 9 + tap];
    };
    uint4 o;
    o.x = h2u(Wv(co0,     kb),     Wv(co0,     kb + 1));
    o.y = h2u(Wv(co0 + 8, kb),     Wv(co0 + 8, kb + 1));
    o.z = k8 ? 0u : h2u(Wv(co0,     kb + 8), Wv(co0,     kb + 9));
    o.w = k8 ? 0u : h2u(Wv(co0 + 8, kb + 8), Wv(co0 + 8, kb + 9));
    out[idx] = o;
}

// Implicit-GEMM ConvGRU half-cell, fp16 MMA, all-half state.
template<int COUT, int L, bool GATES>
__global__ __launch_bounds__(256, 2)
void cell_mma(const float* __restrict__ x, long long x_bs,
              const uint* __restrict__ mirA,   // L1: planes 0..15
              const uint* __restrict__ mirB,   // L1: planes 16..31 ; L0: pairs 1..16
              const uint4* __restrict__ wf,
              const float* __restrict__ bias,
              const uint* __restrict__ zPr,    // cand: packed z read
              const uint* __restrict__ hPr,    // cand: packed h read (blend)
              uint* __restrict__ zPw,          // gates: packed z write
              uint* __restrict__ outP,         // packed out (rh or h mirror)
              float* __restrict__ fout)        // cand final step: fp32 h out
{
    constexpr int NPL2 = (L == 0) ? 20 : 32;
    constexpr int KT16 = (L == 0) ? 2 : 4;
    constexpr int NSL  = (L == 0) ? 3 : 4;
    constexpr int MT   = COUT / 16;   // 4 (gates) or 2 (cand)
    constexpr int N8   = 4;

    extern __shared__ uint Xs[];     // [NPL2][10][40] half2, plane stride PSTR

    const int tid  = threadIdx.x;
    const int lane = tid & 31;
    const int wid  = tid >> 5;       // 0..7 = pixel row within tile
    const int lq   = lane >> 2;
    const int lr   = lane & 3;

    const int b    = blockIdx.z;
    const int row0 = blockIdx.y * 8;
    const int col0 = blockIdx.x * 32;

    // ---- Stage (two cp.async groups: A = pairs 0..7, B = rest) ----
    auto stage = [&](int plLo, int plHi) {
        const int cnt = (plHi - plLo) * 100;
        for (int i = tid; i < cnt; i += 256) {
            const int pl2 = plLo + i / 100;
            const int rem = i % 100;
            const int yy  = rem / 10;
            const int s   = rem - yy * 10;
            const int gr  = row0 + yy - 1;
            const int gcb = col0 - 4 + s * 4;
            const bool ok = (gr >= 0 && gr < HW && gcb >= 0 && gcb < HW);
            const int pix = ok ? (gr * HW + gcb) : 0;
            uint* dst = Xs + pl2 * PSTR + yy * RSTR + s * 4;
            if (L == 0 && pl2 == 0) {
                uint4 v = make_uint4(0, 0, 0, 0);
                if (ok) {
                    const float4 f = *(const float4*)(x + (size_t)b * x_bs + pix);
                    v.x = h2u(f.x, 0.f); v.y = h2u(f.y, 0.f);
                    v.z = h2u(f.z, 0.f); v.w = h2u(f.w, 0.f);
                }
                *(uint4*)dst = v;
            } else if (L == 0 && pl2 > 16) {
                *(uint4*)dst = make_uint4(0, 0, 0, 0);
            } else {
                const uint* src;
                if (L == 0) src = mirB + ((size_t)b * 16 + pl2 - 1) * HW2 + pix;
                else        src = (pl2 < 16)
                                ? mirA + ((size_t)b * 16 + pl2) * HW2 + pix
                                : mirB + ((size_t)b * 16 + pl2 - 16) * HW2 + pix;
                cp16(smem_u32(dst), src, ok);
            }
        }
    };
    stage(0, 8);
    asm volatile("cp.async.commit_group;");
    stage(8, NPL2);
    asm volatile("cp.async.commit_group;");

    float acc[MT][N8][4];
    #pragma unroll
    for (int mt = 0; mt < MT; mt++)
        #pragma unroll
        for (int j = 0; j < N8; j++)
            #pragma unroll
            for (int q = 0; q < 4; q++) acc[mt][j][q] = 0.f;

    auto compute_k16 = [&](int ks) {
        #pragma unroll (MT == 4 ? 3 : 9)
        for (int tap = 0; tap < 9; tap++) {
            const int dy = tap / 3, dx = tap - dy * 3;
            const uint* xb = Xs + (ks * 8 + lr) * PSTR + (wid + dy) * RSTR + dx + 3 + lq;
            uint bf[N8][2];
            #pragma unroll
            for (int j = 0; j < N8; j++) {
                bf[j][0] = xb[j * 8];
                bf[j][1] = xb[j * 8 + 4 * PSTR];
            }
            const uint4* wbase = wf + (tap * NSL + ks) * MT * 32 + lane;
            #pragma unroll
            for (int mt = 0; mt < MT; mt++) {
                const uint4 a = __ldg(wbase + mt * 32);
                #pragma unroll
                for (int j = 0; j < N8; j++)
                    mma16(acc[mt][j], a.x, a.y, a.z, a.w, bf[j][0], bf[j][1]);
            }
        }
    };

    // ---- Phase A: slice 0 while group B still streams ----
    asm volatile("cp.async.wait_group 1;");
    __syncthreads();
    compute_k16(0);

    // ---- Phase B: remaining slices ----
    asm volatile("cp.async.wait_group 0;");
    __syncthreads();
    #pragma unroll
    for (int ks = 1; ks < KT16; ks++) compute_k16(ks);

    if (L == 0) {
        // K8 tail slice: plane pairs 16..19 (k 32..39)
        #pragma unroll (MT == 4 ? 3 : 9)
        for (int tap = 0; tap < 9; tap++) {
            const int dy = tap / 3, dx = tap - dy * 3;
            const uint* xb = Xs + (16 + lr) * PSTR + (wid + dy) * RSTR + dx + 3 + lq;
            uint bf[N8];
            #pragma unroll
            for (int j = 0; j < N8; j++) bf[j] = xb[j * 8];
            const uint4* wbase = wf + (tap * NSL + 2) * MT * 32 + lane;
            #pragma unroll
            for (int mt = 0; mt < MT; mt++) {
                const uint4 a = __ldg(wbase + mt * 32);
                #pragma unroll
                for (int j = 0; j < N8; j++)
                    mma8(acc[mt][j], a.x, a.y, bf[j]);
            }
        }
    }

    // ---- Epilogue ----
    const int py = row0 + wid;
    #pragma unroll
    for (int mt = 0; mt < MT; mt++) {
        #pragma unroll
        for (int j = 0; j < N8; j++) {
            const int px = col0 + j * 8 + 2 * lr;
            const size_t pix = (size_t)py * HW + px;
            #pragma unroll
            for (int h2 = 0; h2 < 2; h2++) {
                const int cc = mt * 16 + lq + h2 * 8;
                const float bv = __ldg(bias + cc);
                float v0 = acc[mt][j][h2 * 2 + 0] + bv;
                float v1 = acc[mt][j][h2 * 2 + 1] + bv;
                const size_t poff = ((size_t)b * 16 + (cc >> 1)) * HW2 + pix;
                auto sel = [&](uint u) -> float {
                    const __half2 hh = *(const __half2*)&u;
                    return __half2float((cc & 1) ? hh.y : hh.x);
                };
                if (GATES) {
                    if (cc < 32) {      // r gate -> packed rh mirror (h from smem)
                        const int slot = ((L == 0) ? 1 : 16) + (cc >> 1);
                        const uint w0 = Xs[slot * PSTR + (wid + 1) * RSTR + (j * 8 + 2 * lr + 4)];
                        const uint w1 = Xs[slot * PSTR + (wid + 1) * RSTR + (j * 8 + 2 * lr + 5)];
                        const float r0 = sigf(v0) * sel(w0);
                        const float r1 = sigf(v1) * sel(w1);
                        const float r0p = __shfl_xor_sync(0xffffffffu, r0, 4);
                        const float r1p = __shfl_xor_sync(0xffffffffu, r1, 4);
                        if (!(lq & 1)) {
                            uint2 wv;
                            wv.x = h2u(r0, r0p);
                            wv.y = h2u(r1, r1p);
                            *(uint2*)(outP + poff) = wv;
                        }
                    } else {            // z gate -> packed z mirror
                        const float z0 = sigf(v0), z1 = sigf(v1);
                        const float z0p = __shfl_xor_sync(0xffffffffu, z0, 4);
                        const float z1p = __shfl_xor_sync(0xffffffffu, z1, 4);
                        if (!(lq & 1)) {
                            const size_t zoff = ((size_t)b * 16 + ((cc - 32) >> 1)) * HW2 + pix;
                            uint2 wv;
                            wv.x = h2u(z0, z0p);
                            wv.y = h2u(z1, z1p);
                            *(uint2*)(zPw + zoff) = wv;
                        }
                    }
                } else {
                    const uint2 zv2 = *(const uint2*)(zPr + poff);
                    const uint2 hv2 = *(const uint2*)(hPr + poff);
                    const float zx0 = sel(zv2.x), zx1 = sel(zv2.y);
                    const float hx0 = sel(hv2.x), hx1 = sel(hv2.y);
                    const float n0 = tanhfast(v0), n1 = tanhfast(v1);
                    const float o0 = hx0 + zx0 * (n0 - hx0);
                    const float o1 = hx1 + zx1 * (n1 - hx1);
                    const float o0p = __shfl_xor_sync(0xffffffffu, o0, 4);
                    const float o1p = __shfl_xor_sync(0xffffffffu, o1, 4);
                    if (!(lq & 1)) {
                        uint2 wv;
                        wv.x = h2u(o0, o0p);
                        wv.y = h2u(o1, o1p);
                        *(uint2*)(outP + poff) = wv;
                    }
                    if (fout) {
                        *(float2*)(fout + ((size_t)b * 32 + cc) * HW2 + pix) =
                            make_float2(o0, o1);
                    }
                }
            }
        }
    }
}

extern "C" void kernel_launch(void* const* d_in, const int* in_sizes, int n_in,
                              void* d_out, int out_size)
{
    const float* seq = (const float*)d_in[0];
    const float* gw0 = (const float*)d_in[1];
    const float* gb0 = (const float*)d_in[2];
    const float* cw0 = (const float*)d_in[3];
    const float* cb0 = (const float*)d_in[4];
    const float* gw1 = (const float*)d_in[5];
    const float* gb1 = (const float*)d_in[6];
    const float* cw1 = (const float*)d_in[7];
    const float* cb1 = (const float*)d_in[8];

    uint *hp0a, *hp0b, *hp1, *rhp0, *rhp1, *zp0, *zp1;
    cudaGetSymbolAddress((void**)&hp0a, g_hp0a);
    cudaGetSymbolAddress((void**)&hp0b, g_hp0b);
    cudaGetSymbolAddress((void**)&hp1, g_hp1);
    cudaGetSymbolAddress((void**)&rhp0, g_rhp0);
    cudaGetSymbolAddress((void**)&rhp1, g_rhp1);
    cudaGetSymbolAddress((void**)&zp0, g_zp0);
    cudaGetSymbolAddress((void**)&zp1, g_zp1);
    uint4 *wfg0, *wfc0, *wfg1, *wfc1;
    cudaGetSymbolAddress((void**)&wfg0, g_wf_g0);
    cudaGetSymbolAddress((void**)&wfc0, g_wf_c0);
    cudaGetSymbolAddress((void**)&wfg1, g_wf_g1);
    cudaGetSymbolAddress((void**)&wfc1, g_wf_c1);

    const int SM0 = 20 * PSTR * 4;   // 32640 B
    const int SM1 = 32 * PSTR * 4;   // 52224 B
    cudaFuncSetAttribute(cell_mma<64, 0, true >, cudaFuncAttributeMaxDynamicSharedMemorySize, SM0);
    cudaFuncSetAttribute(cell_mma<32, 0, false>, cudaFuncAttributeMaxDynamicSharedMemorySize, SM0);
    cudaFuncSetAttribute(cell_mma<64, 1, true >, cudaFuncAttributeMaxDynamicSharedMemorySize, SM1);
    cudaFuncSetAttribute(cell_mma<32, 1, false>, cudaFuncAttributeMaxDynamicSharedMemorySize, SM1);

    // One-time stream/event creation (host resources only; no device allocs).
    static cudaStream_t sA = nullptr, sB = nullptr;
    static cudaEvent_t evFork, evL0c[NT], evJoinB;
    if (!sA) {
        cudaStreamCreateWithFlags(&sA, cudaStreamNonBlocking);
        cudaStreamCreateWithFlags(&sB, cudaStreamNonBlocking);
        cudaEventCreateWithFlags(&evFork, cudaEventDisableTiming);
        for (int t = 0; t < NT; t++)
            cudaEventCreateWithFlags(&evL0c[t], cudaEventDisableTiming);
        cudaEventCreateWithFlags(&evJoinB, cudaEventDisableTiming);
    }

    zero_states_kernel<<<2048, 256>>>();
    prep_all<<<dim3(18, 4), 256>>>(gw0, cw0, gw1, cw1, wfg0, wfc0, wfg1, wfc1);

    // Fork both worker streams off the capture-origin (default) stream.
    cudaEventRecord(evFork, 0);
    cudaStreamWaitEvent(sA, evFork, 0);
    cudaStreamWaitEvent(sB, evFork, 0);

    dim3 grid(HW / 32, HW / 8, NB);  // (4, 16, 8)
    dim3 blk(256);
    const long long seq_bs = (long long)NT * HW2;

    for (int t = 0; t < NT; t++) {
        const float* xt = seq + (size_t)t * HW2;
        // h0 mirror parity: L0c(t) writes hp0[t&1]; L0g(t)/L0c(t) read hp0[(t+1)&1]
        const uint* hp0_rd = (t & 1) ? hp0a : hp0b;
        uint*       hp0_wr = (t & 1) ? hp0b : hp0a;

        // ---- Stream A: layer 0, step t ----
        cell_mma<64, 0, true ><<<grid, blk, SM0, sA>>>(xt, seq_bs, hp0_rd, hp0_rd,
            wfg0, gb0, nullptr, nullptr, zp0, rhp0, nullptr);
        cell_mma<32, 0, false><<<grid, blk, SM0, sA>>>(xt, seq_bs, rhp0, rhp0,
            wfc0, cb0, zp0, hp0_rd, nullptr, hp0_wr, nullptr);
        cudaEventRecord(evL0c[t], sA);

        // ---- Stream B: layer 1, step t (waits on L0c(t); overlaps L0(t+1)) ----
        cudaStreamWaitEvent(sB, evL0c[t], 0);
        cell_mma<64, 1, true ><<<grid, blk, SM1, sB>>>(nullptr, 0, hp0_wr, hp1,
            wfg1, gb1, nullptr, nullptr, zp1, rhp1, nullptr);
        float* fout = (t == NT - 1) ? (float*)d_out : nullptr;
        cell_mma<32, 1, false><<<grid, blk, SM1, sB>>>(nullptr, 0, hp0_wr, rhp1,
            wfc1, cb1, zp1, hp1, nullptr, hp1, fout);
    }

    // Join back to the origin stream (stream B's chain already depends on A's).
    cudaEventRecord(evJoinB, sB);
    cudaStreamWaitEvent(0, evJoinB, 0);
}